// round 4
// baseline (speedup 1.0000x reference)
#include <cuda_runtime.h>
#include <cstdint>

#define NB   512
#define CB   1024
#define VB   68
#define PB   7
#define OB   256   // C/4

// ---------------- scratch (device globals; no allocation allowed) ----------
__device__ float g_S1[NB * CB * 8];   // part-wise sums of x,  padded P->8
__device__ float g_S2[NB * CB * 8];   // part-wise sums of x^2
__device__ float g_Wt[CB * OB];       // transposed conv1 weight: Wt[c][o]
__device__ float g_att[NB * 8];       // softmax attention per (n, p), padded
__device__ float g_part[8 * CB * 2];  // partial BN sums (8 n-chunks)
__device__ float g_scale[CB];
__device__ float g_shift[CB];

// ---------------- compile-time joint -> part mapping -----------------------
__device__ __host__ __forceinline__ constexpr int part_of(int v) {
    return v < 17 ? 0 : v < 22 ? 1 : v < 27 ? 2 : v < 36 ? 3 :
           v < 42 ? 4 : v < 48 ? 5 : 6;
}

template <int VV>
__device__ __forceinline__ void acc_one(float val, float* s1, float* s2) {
    constexpr int j = part_of(VV);
    s1[j] += val;
    s2[j] = fmaf(val, val, s2[j]);
}

template <int I>
__device__ __forceinline__ void acc_loop(const float4* xr, float* s1, float* s2) {
    if constexpr (I < 17) {
        float4 q = __ldg(xr + I);
        acc_one<4 * I + 0>(q.x, s1, s2);
        acc_one<4 * I + 1>(q.y, s1, s2);
        acc_one<4 * I + 2>(q.z, s1, s2);
        acc_one<4 * I + 3>(q.w, s1, s2);
        acc_loop<I + 1>(xr, s1, s2);
    }
}

template <int I>
__device__ __forceinline__ void d_loop(const float4* xr, float4* orow,
                                       const float* m, float sh) {
    if constexpr (I < 17) {
        float4 q = __ldg(xr + I);
        constexpr int j0 = part_of(4 * I + 0);
        constexpr int j1 = part_of(4 * I + 1);
        constexpr int j2 = part_of(4 * I + 2);
        constexpr int j3 = part_of(4 * I + 3);
        q.x = fmaxf(fmaf(q.x, m[j0], sh), 0.f);
        q.y = fmaxf(fmaf(q.y, m[j1], sh), 0.f);
        q.z = fmaxf(fmaf(q.z, m[j2], sh), 0.f);
        q.w = fmaxf(fmaf(q.w, m[j3], sh), 0.f);
        orow[I] = q;
        d_loop<I + 1>(xr, orow, m, sh);
    }
}

// ---------------- kT: transpose conv1_w (O,C) -> (C,O) ---------------------
__global__ void __launch_bounds__(256) kT(const float* __restrict__ w1) {
    int idx = blockIdx.x * 256 + threadIdx.x;      // 0 .. 262143
    int o = idx >> 10;
    int c = idx & 1023;
    g_Wt[c * OB + o] = w1[idx];
}

// ---------------- kA: per-(n,c) part-wise sums of x and x^2 -----------------
__global__ void __launch_bounds__(256) kA(const float* __restrict__ x) {
    int row = blockIdx.x * 256 + threadIdx.x;      // 0 .. N*C-1
    float s1[8] = {0, 0, 0, 0, 0, 0, 0, 0};
    float s2[8] = {0, 0, 0, 0, 0, 0, 0, 0};
    const float4* xr = (const float4*)(x + (size_t)row * VB);
    acc_loop<0>(xr, s1, s2);
    float4* o1 = (float4*)(g_S1 + (size_t)row * 8);
    o1[0] = make_float4(s1[0], s1[1], s1[2], s1[3]);
    o1[1] = make_float4(s1[4], s1[5], s1[6], 0.f);
    float4* o2 = (float4*)(g_S2 + (size_t)row * 8);
    o2[0] = make_float4(s2[0], s2[1], s2[2], s2[3]);
    o2[1] = make_float4(s2[4], s2[5], s2[6], 0.f);
}

// ---------------- kB: conv1 GEMM + avg/max pool + conv2 + softmax -----------
__global__ void __launch_bounds__(256) kB(const float* __restrict__ b1,
                                          const float* __restrict__ w2,
                                          const float* __restrict__ b2c) {
    __shared__ float xs[CB * 8];          // x_parts[c][p] (mean-pooled), padded
    __shared__ float rsum[8][8];
    __shared__ float rmax[8][8];
    __shared__ float satt[8];

    int n = blockIdx.x;
    int t = threadIdx.x;

    // load S1[n] and convert sums -> means (divide by part counts)
    const float4* src = (const float4*)(g_S1 + (size_t)n * (CB * 8));
#pragma unroll
    for (int it = 0; it < 8; it++) {
        int idx = t + it * 256;           // float4 index, 0..2047
        float4 q = __ldg(src + idx);
        if (idx & 1) {                    // p = 4..7
            q.x *= (1.f / 6.f);  q.y *= (1.f / 6.f);
            q.z *= (1.f / 20.f); q.w = 0.f;
        } else {                          // p = 0..3
            q.x *= (1.f / 17.f); q.y *= (1.f / 5.f);
            q.z *= (1.f / 5.f);  q.w *= (1.f / 9.f);
        }
        ((float4*)xs)[idx] = q;
    }
    __syncthreads();

    unsigned xs_base = (unsigned)__cvta_generic_to_shared(xs);
    unsigned long long a0 = 0, a1 = 0, a2 = 0, a3 = 0;  // f32x2 accumulators
    const float* wp = g_Wt + t;           // Wt[c*256 + o], o = t

#pragma unroll 4
    for (int c = 0; c < CB; c++) {
        float w = __ldg(wp + c * OB);
        unsigned long long w2r;
        asm("mov.b64 %0, {%1,%1};" : "=l"(w2r) : "f"(w));
        unsigned long long x01, x23, x45, x67;
        unsigned addr = xs_base + c * 32;
        asm("ld.shared.v2.u64 {%0,%1}, [%2];"    : "=l"(x01), "=l"(x23) : "r"(addr));
        asm("ld.shared.v2.u64 {%0,%1}, [%2+16];" : "=l"(x45), "=l"(x67) : "r"(addr));
        asm("fma.rn.f32x2 %0, %1, %2, %0;" : "+l"(a0) : "l"(x01), "l"(w2r));
        asm("fma.rn.f32x2 %0, %1, %2, %0;" : "+l"(a1) : "l"(x23), "l"(w2r));
        asm("fma.rn.f32x2 %0, %1, %2, %0;" : "+l"(a2) : "l"(x45), "l"(w2r));
        asm("fma.rn.f32x2 %0, %1, %2, %0;" : "+l"(a3) : "l"(x67), "l"(w2r));
    }

    float hs[8];
    asm("mov.b64 {%0,%1}, %2;" : "=f"(hs[0]), "=f"(hs[1]) : "l"(a0));
    asm("mov.b64 {%0,%1}, %2;" : "=f"(hs[2]), "=f"(hs[3]) : "l"(a1));
    asm("mov.b64 {%0,%1}, %2;" : "=f"(hs[4]), "=f"(hs[5]) : "l"(a2));
    asm("mov.b64 {%0,%1}, %2;" : "=f"(hs[6]), "=f"(hs[7]) : "l"(a3));
    float bo = __ldg(b1 + t);
#pragma unroll
    for (int p = 0; p < PB; p++) hs[p] += bo;

    unsigned lane = t & 31, wid = t >> 5;
#pragma unroll
    for (int p = 0; p < PB; p++) {
        float s = hs[p], mm = hs[p];
#pragma unroll
        for (int off = 16; off > 0; off >>= 1) {
            s += __shfl_xor_sync(0xffffffffu, s, off);
            mm = fmaxf(mm, __shfl_xor_sync(0xffffffffu, mm, off));
        }
        if (lane == 0) { rsum[wid][p] = s; rmax[wid][p] = mm; }
    }
    __syncthreads();

    if (t < PB) {
        int p = t;
        float s = 0.f, mm = -3.402823e38f;
#pragma unroll
        for (int w = 0; w < 8; w++) { s += rsum[w][p]; mm = fmaxf(mm, rmax[w][p]); }
        satt[p] = __ldg(w2) * (s * (1.f / 256.f)) + __ldg(w2 + 1) * mm + __ldg(b2c);
    }
    __syncthreads();

    if (t == 0) {
        float mx = -3.402823e38f;
#pragma unroll
        for (int p = 0; p < PB; p++) mx = fmaxf(mx, satt[p]);
        float e[PB];
        float ssum = 0.f;
#pragma unroll
        for (int p = 0; p < PB; p++) { e[p] = expf(satt[p] - mx); ssum += e[p]; }
        float inv = 1.f / ssum;
#pragma unroll
        for (int p = 0; p < PB; p++) g_att[n * 8 + p] = e[p] * inv;
        g_att[n * 8 + 7] = 0.f;
    }
}

// ---------------- kC: per-channel BN sums from part sums --------------------
// grid (4, 8): blockIdx.x -> channel chunk (256 ch), blockIdx.y -> n chunk (64)
__global__ void __launch_bounds__(256) kC() {
    __shared__ float sa[64][8];
    __shared__ float sa2[64][8];
    int c = blockIdx.x * 256 + threadIdx.x;
    int n0 = blockIdx.y * 64;

    if (threadIdx.x < 128) {
        float4 q = __ldg(((const float4*)(g_att + n0 * 8)) + threadIdx.x);
        ((float4*)sa)[threadIdx.x] = q;
        ((float4*)sa2)[threadIdx.x] =
            make_float4(q.x * q.x, q.y * q.y, q.z * q.z, q.w * q.w);
    }
    __syncthreads();

    float sY = 0.f, sY2 = 0.f;
    for (int nn = 0; nn < 64; nn++) {
        size_t base = ((size_t)(n0 + nn) * CB + c) * 8;
        const float4* p1 = (const float4*)(g_S1 + base);
        const float4* p2 = (const float4*)(g_S2 + base);
        float4 q0 = __ldg(p1), q1 = __ldg(p1 + 1);
        float4 r0 = __ldg(p2), r1 = __ldg(p2 + 1);
        const float* a  = sa[nn];
        const float* a2 = sa2[nn];
        sY  = fmaf(q0.x, a[0], fmaf(q0.y, a[1], fmaf(q0.z, a[2], fmaf(q0.w, a[3],
              fmaf(q1.x, a[4], fmaf(q1.y, a[5], fmaf(q1.z, a[6], sY)))))));
        sY2 = fmaf(r0.x, a2[0], fmaf(r0.y, a2[1], fmaf(r0.z, a2[2], fmaf(r0.w, a2[3],
              fmaf(r1.x, a2[4], fmaf(r1.y, a2[5], fmaf(r1.z, a2[6], sY2)))))));
    }
    size_t oidx = ((size_t)blockIdx.y * CB + c) * 2;
    g_part[oidx]     = sY;
    g_part[oidx + 1] = sY2;
}

// ---------------- kC2: reduce partials -> scale/shift -----------------------
__global__ void __launch_bounds__(256) kC2(const float* __restrict__ gamma,
                                           const float* __restrict__ beta) {
    int c = blockIdx.x * 256 + threadIdx.x;
    float sY = 0.f, sY2 = 0.f;
#pragma unroll
    for (int w = 0; w < 8; w++) {
        sY  += g_part[(w * CB + c) * 2];
        sY2 += g_part[(w * CB + c) * 2 + 1];
    }
    const float inv = 1.f / (512.f * 68.f);
    float mean = sY * inv;
    float var = fmaf(-mean, mean, sY2 * inv);
    float sc = gamma[c] * rsqrtf(var + 1e-5f);
    g_scale[c] = sc;
    g_shift[c] = fmaf(-mean, sc, beta[c]);
}

// ---------------- kD: fused attention-scale + BN + residual + ReLU ----------
__global__ void __launch_bounds__(256) kD(const float* __restrict__ x,
                                          float* __restrict__ out) {
    int row = blockIdx.x * 256 + threadIdx.x;  // (n, c)
    int n = row >> 10;
    int c = row & 1023;
    float sc = g_scale[c];
    float sh = g_shift[c];
    const float* at = g_att + n * 8;           // warp-uniform (same n)
    float m[PB];
#pragma unroll
    for (int p = 0; p < PB; p++) m[p] = fmaf(__ldg(at + p), sc, 1.f);
    d_loop<0>((const float4*)(x + (size_t)row * VB),
              (float4*)(out + (size_t)row * VB), m, sh);
}

// ---------------- launch ----------------------------------------------------
extern "C" void kernel_launch(void* const* d_in, const int* in_sizes, int n_in,
                              void* d_out, int out_size) {
    const float* x     = (const float*)d_in[0];  // (512,1024,1,68)
    const float* w1    = (const float*)d_in[1];  // (256,1024)
    const float* b1    = (const float*)d_in[2];  // (256,)
    const float* w2    = (const float*)d_in[3];  // (2,)
    const float* b2    = (const float*)d_in[4];  // scalar
    const float* gamma = (const float*)d_in[5];  // (1024,)
    const float* beta  = (const float*)d_in[6];  // (1024,)
    float* out = (float*)d_out;

    kT<<<CB * OB / 256, 256>>>(w1);
    kA<<<NB * CB / 256, 256>>>(x);
    kB<<<NB, 256>>>(b1, w2, b2);
    kC<<<dim3(4, 8), 256>>>();
    kC2<<<CB / 256, 256>>>(gamma, beta);
    kD<<<NB * CB / 256, 256>>>(x, out);
}

// round 5
// speedup vs baseline: 1.1614x; 1.1614x over previous
#include <cuda_runtime.h>
#include <cstdint>

#define NB   512
#define CB   1024
#define VB   68
#define PB   7
#define OB   256   // C/4

// ---------------- scratch (device globals; no allocation allowed) ----------
__device__ float g_S1[NB * CB * 8];    // part-wise sums of x,  padded P->8
__device__ float g_S2[NB * CB * 8];    // part-wise sums of x^2
__device__ float g_Wt[CB * OB];        // transposed conv1 weight: Wt[c][o]
__device__ float g_att[NB * 8];        // softmax attention per (n, p), padded
__device__ float g_part[32 * CB * 2];  // partial BN sums (32 n-chunks)
__device__ float g_scale[CB];
__device__ float g_shift[CB];

// ---------------- compile-time joint -> part mapping -----------------------
__device__ __host__ __forceinline__ constexpr int part_of(int v) {
    return v < 17 ? 0 : v < 22 ? 1 : v < 27 ? 2 : v < 36 ? 3 :
           v < 42 ? 4 : v < 48 ? 5 : 6;
}

template <int VV>
__device__ __forceinline__ void acc_one(float val, float* s1, float* s2) {
    constexpr int j = part_of(VV);
    s1[j] += val;
    s2[j] = fmaf(val, val, s2[j]);
}

template <int I>
__device__ __forceinline__ void acc_loop(const float4* xr, float* s1, float* s2) {
    if constexpr (I < 17) {
        float4 q = __ldg(xr + I);
        acc_one<4 * I + 0>(q.x, s1, s2);
        acc_one<4 * I + 1>(q.y, s1, s2);
        acc_one<4 * I + 2>(q.z, s1, s2);
        acc_one<4 * I + 3>(q.w, s1, s2);
        acc_loop<I + 1>(xr, s1, s2);
    }
}

template <int I>
__device__ __forceinline__ void d_loop(const float4* xr, float4* orow,
                                       const float* m, float sh) {
    if constexpr (I < 17) {
        float4 q = __ldg(xr + I);
        constexpr int j0 = part_of(4 * I + 0);
        constexpr int j1 = part_of(4 * I + 1);
        constexpr int j2 = part_of(4 * I + 2);
        constexpr int j3 = part_of(4 * I + 3);
        q.x = fmaxf(fmaf(q.x, m[j0], sh), 0.f);
        q.y = fmaxf(fmaf(q.y, m[j1], sh), 0.f);
        q.z = fmaxf(fmaf(q.z, m[j2], sh), 0.f);
        q.w = fmaxf(fmaf(q.w, m[j3], sh), 0.f);
        orow[I] = q;
        d_loop<I + 1>(xr, orow, m, sh);
    }
}

// ---------------- kT: transpose conv1_w (O,C) -> (C,O) ---------------------
__global__ void __launch_bounds__(256) kT(const float* __restrict__ w1) {
    int idx = blockIdx.x * 256 + threadIdx.x;      // 0 .. 262143
    int o = idx >> 10;
    int c = idx & 1023;
    g_Wt[c * OB + o] = w1[idx];
}

// ---------------- kA: per-(n,c) part-wise sums of x and x^2 -----------------
__global__ void __launch_bounds__(256) kA(const float* __restrict__ x) {
    int row = blockIdx.x * 256 + threadIdx.x;      // 0 .. N*C-1
    float s1[8] = {0, 0, 0, 0, 0, 0, 0, 0};
    float s2[8] = {0, 0, 0, 0, 0, 0, 0, 0};
    const float4* xr = (const float4*)(x + (size_t)row * VB);
    acc_loop<0>(xr, s1, s2);
    float4* o1 = (float4*)(g_S1 + (size_t)row * 8);
    o1[0] = make_float4(s1[0], s1[1], s1[2], s1[3]);
    o1[1] = make_float4(s1[4], s1[5], s1[6], 0.f);
    float4* o2 = (float4*)(g_S2 + (size_t)row * 8);
    o2[0] = make_float4(s2[0], s2[1], s2[2], s2[3]);
    o2[1] = make_float4(s2[4], s2[5], s2[6], 0.f);
}

// ---------------- kB: conv1 GEMM + avg/max pool + conv2 + softmax -----------
// One block handles TWO samples (n0, n0+1); c is processed in 2 chunks of 512
// staged through 32 KB of SMEM. This halves the L2 traffic on W vs one-n
// blocks and gives grid=256 (>= #SMs).
__global__ void __launch_bounds__(256) kB(const float* __restrict__ b1,
                                          const float* __restrict__ w2,
                                          const float* __restrict__ b2c) {
    __shared__ float xs[2][512][8];       // x_parts (mean-pooled) chunk, 2 n's
    __shared__ float rsum[2][8][8];
    __shared__ float rmax[2][8][8];
    __shared__ float satt[2][8];

    int n0 = blockIdx.x * 2;
    int t = threadIdx.x;

    unsigned long long acc[2][4] = {{0, 0, 0, 0}, {0, 0, 0, 0}};
    unsigned xs_base = (unsigned)__cvta_generic_to_shared(xs);

    for (int cc = 0; cc < 2; cc++) {
        int cbase = cc * 512;
        // stage S1 chunk -> smem, converting part sums -> part means
#pragma unroll
        for (int nn = 0; nn < 2; nn++) {
            const float4* src = (const float4*)(
                g_S1 + ((size_t)(n0 + nn) * CB + cbase) * 8);
            float4* dst = (float4*)xs[nn];
#pragma unroll
            for (int it = 0; it < 4; it++) {
                int idx = t + it * 256;   // float4 index, 0..1023 (2 per c)
                float4 q = __ldg(src + idx);
                if (idx & 1) {            // p = 4..7
                    q.x *= (1.f / 6.f);  q.y *= (1.f / 6.f);
                    q.z *= (1.f / 20.f); q.w = 0.f;
                } else {                  // p = 0..3
                    q.x *= (1.f / 17.f); q.y *= (1.f / 5.f);
                    q.z *= (1.f / 5.f);  q.w *= (1.f / 9.f);
                }
                dst[idx] = q;
            }
        }
        __syncthreads();

        const float* wp = g_Wt + (size_t)cbase * OB + t;   // o = t
#pragma unroll 4
        for (int c = 0; c < 512; c++) {
            float w = __ldg(wp + c * OB);
            unsigned long long w2r;
            asm("mov.b64 %0, {%1,%1};" : "=l"(w2r) : "f"(w));
            unsigned a0 = xs_base + c * 32;            // xs[0][c]
            unsigned a1 = a0 + 512 * 32;               // xs[1][c]
            unsigned long long x0, x1, x2, x3, y0, y1, y2, y3;
            asm("ld.shared.v2.u64 {%0,%1}, [%2];"    : "=l"(x0), "=l"(x1) : "r"(a0));
            asm("ld.shared.v2.u64 {%0,%1}, [%2+16];" : "=l"(x2), "=l"(x3) : "r"(a0));
            asm("ld.shared.v2.u64 {%0,%1}, [%2];"    : "=l"(y0), "=l"(y1) : "r"(a1));
            asm("ld.shared.v2.u64 {%0,%1}, [%2+16];" : "=l"(y2), "=l"(y3) : "r"(a1));
            asm("fma.rn.f32x2 %0, %1, %2, %0;" : "+l"(acc[0][0]) : "l"(x0), "l"(w2r));
            asm("fma.rn.f32x2 %0, %1, %2, %0;" : "+l"(acc[0][1]) : "l"(x1), "l"(w2r));
            asm("fma.rn.f32x2 %0, %1, %2, %0;" : "+l"(acc[0][2]) : "l"(x2), "l"(w2r));
            asm("fma.rn.f32x2 %0, %1, %2, %0;" : "+l"(acc[0][3]) : "l"(x3), "l"(w2r));
            asm("fma.rn.f32x2 %0, %1, %2, %0;" : "+l"(acc[1][0]) : "l"(y0), "l"(w2r));
            asm("fma.rn.f32x2 %0, %1, %2, %0;" : "+l"(acc[1][1]) : "l"(y1), "l"(w2r));
            asm("fma.rn.f32x2 %0, %1, %2, %0;" : "+l"(acc[1][2]) : "l"(y2), "l"(w2r));
            asm("fma.rn.f32x2 %0, %1, %2, %0;" : "+l"(acc[1][3]) : "l"(y3), "l"(w2r));
        }
        __syncthreads();
    }

    // epilogue: bias, channel avg/max pooling, conv2, softmax — per sample
    float bo = __ldg(b1 + t);
    unsigned lane = t & 31, wid = t >> 5;

#pragma unroll
    for (int nn = 0; nn < 2; nn++) {
        float hs[8];
        asm("mov.b64 {%0,%1}, %2;" : "=f"(hs[0]), "=f"(hs[1]) : "l"(acc[nn][0]));
        asm("mov.b64 {%0,%1}, %2;" : "=f"(hs[2]), "=f"(hs[3]) : "l"(acc[nn][1]));
        asm("mov.b64 {%0,%1}, %2;" : "=f"(hs[4]), "=f"(hs[5]) : "l"(acc[nn][2]));
        asm("mov.b64 {%0,%1}, %2;" : "=f"(hs[6]), "=f"(hs[7]) : "l"(acc[nn][3]));
#pragma unroll
        for (int p = 0; p < PB; p++) hs[p] += bo;
#pragma unroll
        for (int p = 0; p < PB; p++) {
            float s = hs[p], mm = hs[p];
#pragma unroll
            for (int off = 16; off > 0; off >>= 1) {
                s += __shfl_xor_sync(0xffffffffu, s, off);
                mm = fmaxf(mm, __shfl_xor_sync(0xffffffffu, mm, off));
            }
            if (lane == 0) { rsum[nn][wid][p] = s; rmax[nn][wid][p] = mm; }
        }
    }
    __syncthreads();

    {
        int nn = (t >= 32) ? 1 : 0;
        int p = t & 31;
        if (p < PB && t < 64) {
            float s = 0.f, mm = -3.402823e38f;
#pragma unroll
            for (int w = 0; w < 8; w++) {
                s += rsum[nn][w][p];
                mm = fmaxf(mm, rmax[nn][w][p]);
            }
            satt[nn][p] = __ldg(w2) * (s * (1.f / 256.f)) +
                          __ldg(w2 + 1) * mm + __ldg(b2c);
        }
    }
    __syncthreads();

    if (t == 0 || t == 32) {
        int nn = (t >= 32) ? 1 : 0;
        float mx = -3.402823e38f;
#pragma unroll
        for (int p = 0; p < PB; p++) mx = fmaxf(mx, satt[nn][p]);
        float e[PB];
        float ssum = 0.f;
#pragma unroll
        for (int p = 0; p < PB; p++) { e[p] = expf(satt[nn][p] - mx); ssum += e[p]; }
        float inv = 1.f / ssum;
#pragma unroll
        for (int p = 0; p < PB; p++) g_att[(n0 + nn) * 8 + p] = e[p] * inv;
        g_att[(n0 + nn) * 8 + 7] = 0.f;
    }
}

// ---------------- kC: per-channel BN sums from part sums --------------------
// grid (4, 32): blockIdx.x -> channel chunk (256 ch), blockIdx.y -> n chunk (16)
__global__ void __launch_bounds__(256) kC() {
    __shared__ float sa[16][8];
    __shared__ float sa2[16][8];
    int c = blockIdx.x * 256 + threadIdx.x;
    int n0 = blockIdx.y * 16;

    if (threadIdx.x < 32) {
        float4 q = __ldg(((const float4*)(g_att + n0 * 8)) + threadIdx.x);
        ((float4*)sa)[threadIdx.x] = q;
        ((float4*)sa2)[threadIdx.x] =
            make_float4(q.x * q.x, q.y * q.y, q.z * q.z, q.w * q.w);
    }
    __syncthreads();

    float sY = 0.f, sY2 = 0.f;
#pragma unroll 4
    for (int nn = 0; nn < 16; nn++) {
        size_t base = ((size_t)(n0 + nn) * CB + c) * 8;
        const float4* p1 = (const float4*)(g_S1 + base);
        const float4* p2 = (const float4*)(g_S2 + base);
        float4 q0 = __ldg(p1), q1 = __ldg(p1 + 1);
        float4 r0 = __ldg(p2), r1 = __ldg(p2 + 1);
        const float* a  = sa[nn];
        const float* a2 = sa2[nn];
        sY  = fmaf(q0.x, a[0], fmaf(q0.y, a[1], fmaf(q0.z, a[2], fmaf(q0.w, a[3],
              fmaf(q1.x, a[4], fmaf(q1.y, a[5], fmaf(q1.z, a[6], sY)))))));
        sY2 = fmaf(r0.x, a2[0], fmaf(r0.y, a2[1], fmaf(r0.z, a2[2], fmaf(r0.w, a2[3],
              fmaf(r1.x, a2[4], fmaf(r1.y, a2[5], fmaf(r1.z, a2[6], sY2)))))));
    }
    size_t oidx = ((size_t)blockIdx.y * CB + c) * 2;
    g_part[oidx]     = sY;
    g_part[oidx + 1] = sY2;
}

// ---------------- kC2: reduce partials -> scale/shift -----------------------
__global__ void __launch_bounds__(256) kC2(const float* __restrict__ gamma,
                                           const float* __restrict__ beta) {
    int c = blockIdx.x * 256 + threadIdx.x;
    float sY = 0.f, sY2 = 0.f;
#pragma unroll
    for (int w = 0; w < 32; w++) {
        sY  += g_part[(w * CB + c) * 2];
        sY2 += g_part[(w * CB + c) * 2 + 1];
    }
    const float inv = 1.f / (512.f * 68.f);
    float mean = sY * inv;
    float var = fmaf(-mean, mean, sY2 * inv);
    float sc = gamma[c] * rsqrtf(var + 1e-5f);
    g_scale[c] = sc;
    g_shift[c] = fmaf(-mean, sc, beta[c]);
}

// ---------------- kD: fused attention-scale + BN + residual + ReLU ----------
__global__ void __launch_bounds__(256) kD(const float* __restrict__ x,
                                          float* __restrict__ out) {
    int row = blockIdx.x * 256 + threadIdx.x;  // (n, c)
    int n = row >> 10;
    int c = row & 1023;
    float sc = g_scale[c];
    float sh = g_shift[c];
    const float* at = g_att + n * 8;           // warp-uniform (same n)
    float m[PB];
#pragma unroll
    for (int p = 0; p < PB; p++) m[p] = fmaf(__ldg(at + p), sc, 1.f);
    d_loop<0>((const float4*)(x + (size_t)row * VB),
              (float4*)(out + (size_t)row * VB), m, sh);
}

// ---------------- launch ----------------------------------------------------
extern "C" void kernel_launch(void* const* d_in, const int* in_sizes, int n_in,
                              void* d_out, int out_size) {
    const float* x     = (const float*)d_in[0];  // (512,1024,1,68)
    const float* w1    = (const float*)d_in[1];  // (256,1024)
    const float* b1    = (const float*)d_in[2];  // (256,)
    const float* w2    = (const float*)d_in[3];  // (2,)
    const float* b2    = (const float*)d_in[4];  // scalar
    const float* gamma = (const float*)d_in[5];  // (1024,)
    const float* beta  = (const float*)d_in[6];  // (1024,)
    float* out = (float*)d_out;

    kT<<<CB * OB / 256, 256>>>(w1);
    kA<<<NB * CB / 256, 256>>>(x);
    kB<<<NB / 2, 256>>>(b1, w2, b2);
    kC<<<dim3(4, 32), 256>>>();
    kC2<<<CB / 256, 256>>>(gamma, beta);
    kD<<<NB * CB / 256, 256>>>(x, out);
}

// round 6
// speedup vs baseline: 1.5417x; 1.3274x over previous
#include <cuda_runtime.h>
#include <cstdint>

#define NB   512
#define CB   1024
#define VB   68
#define PB   7
#define OB   256   // C/4
#define NP   4096  // NB * 8 (p padded to 8)

// ---------------- scratch (device globals; no allocation allowed) ----------
__device__ float  g_S1[NB * CB * 8];    // part-wise sums of x,  padded P->8
__device__ float  g_S2[NB * CB * 8];    // part-wise sums of x^2
__device__ float  g_X [CB * NP];        // mean-pooled x_parts, [c][np]
__device__ float  g_Wt[CB * OB];        // transposed conv1 weight: Wt[c][o]
__device__ float2 g_pool[2 * NP];       // per o-half: (sum, max) over 128 o
__device__ float  g_att[NB * 8];        // softmax attention per (n, p), padded
__device__ float  g_part[32 * CB * 2];  // partial BN sums (32 n-chunks)
__device__ float  g_scale[CB];
__device__ float  g_shift[CB];

// ---------------- compile-time joint -> part mapping -----------------------
__device__ __host__ __forceinline__ constexpr int part_of(int v) {
    return v < 17 ? 0 : v < 22 ? 1 : v < 27 ? 2 : v < 36 ? 3 :
           v < 42 ? 4 : v < 48 ? 5 : 6;
}

template <int VV>
__device__ __forceinline__ void acc_one(float val, float* s1, float* s2) {
    constexpr int j = part_of(VV);
    s1[j] += val;
    s2[j] = fmaf(val, val, s2[j]);
}

template <int I>
__device__ __forceinline__ void acc_loop(const float4* xr, float* s1, float* s2) {
    if constexpr (I < 17) {
        float4 q = __ldg(xr + I);
        acc_one<4 * I + 0>(q.x, s1, s2);
        acc_one<4 * I + 1>(q.y, s1, s2);
        acc_one<4 * I + 2>(q.z, s1, s2);
        acc_one<4 * I + 3>(q.w, s1, s2);
        acc_loop<I + 1>(xr, s1, s2);
    }
}

template <int I>
__device__ __forceinline__ void d_loop(const float4* xr, float4* orow,
                                       const float* m, float sh) {
    if constexpr (I < 17) {
        float4 q = __ldg(xr + I);
        constexpr int j0 = part_of(4 * I + 0);
        constexpr int j1 = part_of(4 * I + 1);
        constexpr int j2 = part_of(4 * I + 2);
        constexpr int j3 = part_of(4 * I + 3);
        q.x = fmaxf(fmaf(q.x, m[j0], sh), 0.f);
        q.y = fmaxf(fmaf(q.y, m[j1], sh), 0.f);
        q.z = fmaxf(fmaf(q.z, m[j2], sh), 0.f);
        q.w = fmaxf(fmaf(q.w, m[j3], sh), 0.f);
        orow[I] = q;
        d_loop<I + 1>(xr, orow, m, sh);
    }
}

// ---------------- kT: transpose conv1_w (O,C) -> (C,O) ---------------------
__global__ void __launch_bounds__(256) kT(const float* __restrict__ w1) {
    int idx = blockIdx.x * 256 + threadIdx.x;      // 0 .. 262143
    int o = idx >> 10;
    int c = idx & 1023;
    g_Wt[c * OB + o] = w1[idx];
}

// ---------------- kA: part sums of x / x^2 + transposed means --------------
__global__ void __launch_bounds__(256) kA(const float* __restrict__ x) {
    int row = blockIdx.x * 256 + threadIdx.x;      // 0 .. N*C-1
    int n = row >> 10;
    int c = row & 1023;
    float s1[8] = {0, 0, 0, 0, 0, 0, 0, 0};
    float s2[8] = {0, 0, 0, 0, 0, 0, 0, 0};
    const float4* xr = (const float4*)(x + (size_t)row * VB);
    acc_loop<0>(xr, s1, s2);
    float4* o1 = (float4*)(g_S1 + (size_t)row * 8);
    o1[0] = make_float4(s1[0], s1[1], s1[2], s1[3]);
    o1[1] = make_float4(s1[4], s1[5], s1[6], 0.f);
    float4* o2 = (float4*)(g_S2 + (size_t)row * 8);
    o2[0] = make_float4(s2[0], s2[1], s2[2], s2[3]);
    o2[1] = make_float4(s2[4], s2[5], s2[6], 0.f);
    // transposed mean-pooled layout for the GEMM: g_X[c][n*8+p]
    float4* gx = (float4*)(g_X + (size_t)c * NP + n * 8);
    gx[0] = make_float4(s1[0] * (1.f / 17.f), s1[1] * (1.f / 5.f),
                        s1[2] * (1.f / 5.f),  s1[3] * (1.f / 9.f));
    gx[1] = make_float4(s1[4] * (1.f / 6.f),  s1[5] * (1.f / 6.f),
                        s1[6] * (1.f / 20.f), 0.f);
}

// ---------------- kB: tiled SGEMM h = Wt^T * X + pooled epilogue -----------
// grid (64, 2): x = np-tile (64 np = 8 n), y = o-half (128 o). 128 threads.
// Thread (tx=t&15, ty=t>>4) computes an 8o x 8np register tile.
#define FMA2(A, X, W) \
    asm("fma.rn.f32x2 %0, %1, %2, %0;" : "+l"(A) : "l"(X), "l"(W))

__global__ void __launch_bounds__(128) kB(const float* __restrict__ b1) {
    __shared__ float Wt_sh[2][32][128];   // [buf][c][o]   32 KB
    __shared__ float X_sh [2][32][64];    // [buf][c][np]  16 KB
    int t = threadIdx.x;
    int npt = blockIdx.x;                 // np tile
    int oh  = blockIdx.y;                 // o half
    int tx = t & 15, ty = t >> 4;

    unsigned w_base = (unsigned)__cvta_generic_to_shared(Wt_sh);
    unsigned x_base = (unsigned)__cvta_generic_to_shared(X_sh);
    const float* gW = g_Wt + oh * 128;
    const float* gX = g_X + npt * 64;

    auto load_chunk = [&](int k, int buf) {
#pragma unroll
        for (int i = 0; i < 8; i++) {          // W: 1024 float4
            int idx = t + i * 128;
            int cr = idx >> 5, c4 = idx & 31;
            const float* src = gW + (size_t)(k * 32 + cr) * OB + c4 * 4;
            unsigned dst = w_base + (((buf * 32 + cr) * 128) + c4 * 4) * 4;
            asm volatile("cp.async.cg.shared.global [%0], [%1], 16;"
                         :: "r"(dst), "l"(src));
        }
#pragma unroll
        for (int i = 0; i < 4; i++) {          // X: 512 float4
            int idx = t + i * 128;
            int cr = idx >> 4, c4 = idx & 15;
            const float* src = gX + (size_t)(k * 32 + cr) * NP + c4 * 4;
            unsigned dst = x_base + (((buf * 32 + cr) * 64) + c4 * 4) * 4;
            asm volatile("cp.async.cg.shared.global [%0], [%1], 16;"
                         :: "r"(dst), "l"(src));
        }
        asm volatile("cp.async.commit_group;");
    };

    unsigned long long acc[8][4];
#pragma unroll
    for (int i = 0; i < 8; i++)
#pragma unroll
        for (int j = 0; j < 4; j++) acc[i][j] = 0ULL;

    load_chunk(0, 0);
    for (int k = 0; k < 32; k++) {
        int buf = k & 1;
        if (k < 31) {
            load_chunk(k + 1, buf ^ 1);
            asm volatile("cp.async.wait_group 1;");
        } else {
            asm volatile("cp.async.wait_group 0;");
        }
        __syncthreads();

        unsigned wrow = w_base + ((buf * 32) * 128 + tx * 8) * 4;
        unsigned xrow = x_base + ((buf * 32) * 64 + ty * 8) * 4;

        // register-pipelined inner loop over the 32 c's of this chunk
        float4 wa, wb;
        unsigned long long x01, x23, x45, x67;
        asm("ld.shared.v4.f32 {%0,%1,%2,%3}, [%4];"
            : "=f"(wa.x), "=f"(wa.y), "=f"(wa.z), "=f"(wa.w) : "r"(wrow));
        asm("ld.shared.v4.f32 {%0,%1,%2,%3}, [%4+16];"
            : "=f"(wb.x), "=f"(wb.y), "=f"(wb.z), "=f"(wb.w) : "r"(wrow));
        asm("ld.shared.v2.u64 {%0,%1}, [%2];"    : "=l"(x01), "=l"(x23) : "r"(xrow));
        asm("ld.shared.v2.u64 {%0,%1}, [%2+16];" : "=l"(x45), "=l"(x67) : "r"(xrow));

#pragma unroll 8
        for (int cc = 0; cc < 32; cc++) {
            float4 wan, wbn;
            unsigned long long n01, n23, n45, n67;
            if (cc < 31) {
                unsigned wr = wrow + (cc + 1) * 128 * 4;
                unsigned xr = xrow + (cc + 1) * 64 * 4;
                asm("ld.shared.v4.f32 {%0,%1,%2,%3}, [%4];"
                    : "=f"(wan.x), "=f"(wan.y), "=f"(wan.z), "=f"(wan.w) : "r"(wr));
                asm("ld.shared.v4.f32 {%0,%1,%2,%3}, [%4+16];"
                    : "=f"(wbn.x), "=f"(wbn.y), "=f"(wbn.z), "=f"(wbn.w) : "r"(wr));
                asm("ld.shared.v2.u64 {%0,%1}, [%2];"    : "=l"(n01), "=l"(n23) : "r"(xr));
                asm("ld.shared.v2.u64 {%0,%1}, [%2+16];" : "=l"(n45), "=l"(n67) : "r"(xr));
            }
            unsigned long long ws;
#define O_STEP(OI, WV)                                            \
            asm("mov.b64 %0, {%1,%1};" : "=l"(ws) : "f"(WV));     \
            FMA2(acc[OI][0], x01, ws); FMA2(acc[OI][1], x23, ws); \
            FMA2(acc[OI][2], x45, ws); FMA2(acc[OI][3], x67, ws);
            O_STEP(0, wa.x) O_STEP(1, wa.y) O_STEP(2, wa.z) O_STEP(3, wa.w)
            O_STEP(4, wb.x) O_STEP(5, wb.y) O_STEP(6, wb.z) O_STEP(7, wb.w)
#undef O_STEP
            wa = wan; wb = wbn;
            x01 = n01; x23 = n23; x45 = n45; x67 = n67;
        }
        __syncthreads();
    }

    // ---- epilogue: bias, per-np sum & max over this half's 128 o ----
    float bs[8];
#pragma unroll
    for (int i = 0; i < 8; i++) bs[i] = __ldg(b1 + oh * 128 + tx * 8 + i);

    float s[8], mx[8];
#pragma unroll
    for (int j = 0; j < 8; j++) { s[j] = 0.f; mx[j] = -3.402823e38f; }
#pragma unroll
    for (int oi = 0; oi < 8; oi++) {
#pragma unroll
        for (int j = 0; j < 4; j++) {
            float lo, hi;
            asm("mov.b64 {%0,%1}, %2;" : "=f"(lo), "=f"(hi) : "l"(acc[oi][j]));
            lo += bs[oi]; hi += bs[oi];
            s[2 * j]     += lo; mx[2 * j]     = fmaxf(mx[2 * j], lo);
            s[2 * j + 1] += hi; mx[2 * j + 1] = fmaxf(mx[2 * j + 1], hi);
        }
    }
    // reduce across the 16 o-threads (a half-warp: xor offsets < 16)
#pragma unroll
    for (int off = 8; off > 0; off >>= 1) {
#pragma unroll
        for (int j = 0; j < 8; j++) {
            s[j]  += __shfl_xor_sync(0xffffffffu, s[j], off);
            mx[j] = fmaxf(mx[j], __shfl_xor_sync(0xffffffffu, mx[j], off));
        }
    }
    int npb = npt * 64 + ty * 8;
#pragma unroll
    for (int j = 0; j < 8; j++)
        if (tx == j) g_pool[oh * NP + npb + j] = make_float2(s[j], mx[j]);
}

// ---------------- kB2: combine o-halves, conv2, softmax -> g_att -----------
__global__ void __launch_bounds__(256) kB2(const float* __restrict__ w2,
                                           const float* __restrict__ b2c) {
    int n = blockIdx.x * 256 + threadIdx.x;   // 0..511
    float w2a = __ldg(w2), w2b = __ldg(w2 + 1), bb = __ldg(b2c);
    float lg[PB];
    float mxv = -3.402823e38f;
#pragma unroll
    for (int p = 0; p < PB; p++) {
        float2 a0 = g_pool[n * 8 + p];
        float2 a1 = g_pool[NP + n * 8 + p];
        float avg = (a0.x + a1.x) * (1.f / 256.f);
        float m = fmaxf(a0.y, a1.y);
        lg[p] = fmaf(w2a, avg, fmaf(w2b, m, bb));
        mxv = fmaxf(mxv, lg[p]);
    }
    float e[PB], ss = 0.f;
#pragma unroll
    for (int p = 0; p < PB; p++) { e[p] = expf(lg[p] - mxv); ss += e[p]; }
    float inv = 1.f / ss;
#pragma unroll
    for (int p = 0; p < PB; p++) g_att[n * 8 + p] = e[p] * inv;
    g_att[n * 8 + 7] = 0.f;
}

// ---------------- kC: per-channel BN sums from part sums --------------------
__global__ void __launch_bounds__(256) kC() {
    __shared__ float sa[16][8];
    __shared__ float sa2[16][8];
    int c = blockIdx.x * 256 + threadIdx.x;
    int n0 = blockIdx.y * 16;

    if (threadIdx.x < 32) {
        float4 q = __ldg(((const float4*)(g_att + n0 * 8)) + threadIdx.x);
        ((float4*)sa)[threadIdx.x] = q;
        ((float4*)sa2)[threadIdx.x] =
            make_float4(q.x * q.x, q.y * q.y, q.z * q.z, q.w * q.w);
    }
    __syncthreads();

    float sY = 0.f, sY2 = 0.f;
#pragma unroll 4
    for (int nn = 0; nn < 16; nn++) {
        size_t base = ((size_t)(n0 + nn) * CB + c) * 8;
        const float4* p1 = (const float4*)(g_S1 + base);
        const float4* p2 = (const float4*)(g_S2 + base);
        float4 q0 = __ldg(p1), q1 = __ldg(p1 + 1);
        float4 r0 = __ldg(p2), r1 = __ldg(p2 + 1);
        const float* a  = sa[nn];
        const float* a2 = sa2[nn];
        sY  = fmaf(q0.x, a[0], fmaf(q0.y, a[1], fmaf(q0.z, a[2], fmaf(q0.w, a[3],
              fmaf(q1.x, a[4], fmaf(q1.y, a[5], fmaf(q1.z, a[6], sY)))))));
        sY2 = fmaf(r0.x, a2[0], fmaf(r0.y, a2[1], fmaf(r0.z, a2[2], fmaf(r0.w, a2[3],
              fmaf(r1.x, a2[4], fmaf(r1.y, a2[5], fmaf(r1.z, a2[6], sY2)))))));
    }
    size_t oidx = ((size_t)blockIdx.y * CB + c) * 2;
    g_part[oidx]     = sY;
    g_part[oidx + 1] = sY2;
}

// ---------------- kC2: reduce partials -> scale/shift -----------------------
__global__ void __launch_bounds__(256) kC2(const float* __restrict__ gamma,
                                           const float* __restrict__ beta) {
    int c = blockIdx.x * 256 + threadIdx.x;
    float sY = 0.f, sY2 = 0.f;
#pragma unroll
    for (int w = 0; w < 32; w++) {
        sY  += g_part[(w * CB + c) * 2];
        sY2 += g_part[(w * CB + c) * 2 + 1];
    }
    const float inv = 1.f / (512.f * 68.f);
    float mean = sY * inv;
    float var = fmaf(-mean, mean, sY2 * inv);
    float sc = gamma[c] * rsqrtf(var + 1e-5f);
    g_scale[c] = sc;
    g_shift[c] = fmaf(-mean, sc, beta[c]);
}

// ---------------- kD: fused attention-scale + BN + residual + ReLU ----------
__global__ void __launch_bounds__(256) kD(const float* __restrict__ x,
                                          float* __restrict__ out) {
    int row = blockIdx.x * 256 + threadIdx.x;  // (n, c)
    int n = row >> 10;
    int c = row & 1023;
    float sc = g_scale[c];
    float sh = g_shift[c];
    const float* at = g_att + n * 8;
    float m[PB];
#pragma unroll
    for (int p = 0; p < PB; p++) m[p] = fmaf(__ldg(at + p), sc, 1.f);
    d_loop<0>((const float4*)(x + (size_t)row * VB),
              (float4*)(out + (size_t)row * VB), m, sh);
}

// ---------------- launch ----------------------------------------------------
extern "C" void kernel_launch(void* const* d_in, const int* in_sizes, int n_in,
                              void* d_out, int out_size) {
    const float* x     = (const float*)d_in[0];  // (512,1024,1,68)
    const float* w1    = (const float*)d_in[1];  // (256,1024)
    const float* b1    = (const float*)d_in[2];  // (256,)
    const float* w2    = (const float*)d_in[3];  // (2,)
    const float* b2    = (const float*)d_in[4];  // scalar
    const float* gamma = (const float*)d_in[5];  // (1024,)
    const float* beta  = (const float*)d_in[6];  // (1024,)
    float* out = (float*)d_out;

    kT<<<CB * OB / 256, 256>>>(w1);
    kA<<<NB * CB / 256, 256>>>(x);
    kB<<<dim3(64, 2), 128>>>(b1);
    kB2<<<2, 256>>>(w2, b2);
    kC<<<dim3(4, 32), 256>>>();
    kC2<<<CB / 256, 256>>>(gamma, beta);
    kD<<<NB * CB / 256, 256>>>(x, out);
}

// round 8
// speedup vs baseline: 1.8530x; 1.2019x over previous
#include <cuda_runtime.h>
#include <cstdint>

#define NB   512
#define CB   1024
#define VB   68
#define PB   7
#define OB   256   // C/4
#define NP   4096  // NB * 8 (p padded to 8)

// ---------------- scratch (device globals; no allocation allowed) ----------
__device__ float  g_S1[NB * CB * 8];    // part-wise sums of x,  padded P->8
__device__ float  g_S2[NB * CB * 8];    // part-wise sums of x^2
__device__ float  g_X [CB * NP];        // mean-pooled x_parts, [c][np]
__device__ float  g_Wt[CB * OB];        // transposed conv1 weight: Wt[c][o]
__device__ float2 g_pool[2 * NP];       // per o-half: (sum, max) over 128 o
__device__ float  g_att[NB * 8];        // softmax attention per (n, p), padded
__device__ float  g_part[32 * CB * 2];  // partial BN sums (32 n-chunks)
__device__ float  g_scale[CB];
__device__ float  g_shift[CB];

// ---------------- compile-time joint -> part mapping -----------------------
__device__ __host__ __forceinline__ constexpr int part_of(int v) {
    return v < 17 ? 0 : v < 22 ? 1 : v < 27 ? 2 : v < 36 ? 3 :
           v < 42 ? 4 : v < 48 ? 5 : 6;
}

template <int VV>
__device__ __forceinline__ void acc_one(float val, float* s1, float* s2) {
    constexpr int j = part_of(VV);
    s1[j] += val;
    s2[j] = fmaf(val, val, s2[j]);
}

// smem-based accumulate (conflict-free stride-17 LDS.128)
template <int I>
__device__ __forceinline__ void acc_loop_s(const float4* xr, float* s1, float* s2) {
    if constexpr (I < 17) {
        float4 q = xr[I];
        acc_one<4 * I + 0>(q.x, s1, s2);
        acc_one<4 * I + 1>(q.y, s1, s2);
        acc_one<4 * I + 2>(q.z, s1, s2);
        acc_one<4 * I + 3>(q.w, s1, s2);
        acc_loop_s<I + 1>(xr, s1, s2);
    }
}

// smem-based elementwise (in-place)
template <int I>
__device__ __forceinline__ void d_loop_s(float4* xr, const float* m, float sh) {
    if constexpr (I < 17) {
        float4 q = xr[I];
        constexpr int j0 = part_of(4 * I + 0);
        constexpr int j1 = part_of(4 * I + 1);
        constexpr int j2 = part_of(4 * I + 2);
        constexpr int j3 = part_of(4 * I + 3);
        q.x = fmaxf(fmaf(q.x, m[j0], sh), 0.f);
        q.y = fmaxf(fmaf(q.y, m[j1], sh), 0.f);
        q.z = fmaxf(fmaf(q.z, m[j2], sh), 0.f);
        q.w = fmaxf(fmaf(q.w, m[j3], sh), 0.f);
        xr[I] = q;
        d_loop_s<I + 1>(xr, m, sh);
    }
}

// ---------------- kAT: part sums (smem-staged, coalesced) + W transpose -----
// blocks [0, 4096): kA over 128 rows each; blocks [4096, 6144): kT.
__global__ void __launch_bounds__(128) kAT(const float* __restrict__ x,
                                           const float* __restrict__ w1) {
    int t = threadIdx.x;
    if (blockIdx.x >= 4096) {              // ---- transpose conv1_w ----
        int idx = (blockIdx.x - 4096) * 128 + t;   // 0 .. 262143
        int o = idx >> 10;
        int c = idx & 1023;
        g_Wt[c * OB + o] = w1[idx];
        return;
    }
    __shared__ float4 sm[128 * 17];        // 128 rows x 68 floats = 34.8 KB
    const float4* gx = (const float4*)x + (size_t)blockIdx.x * (128 * 17);
#pragma unroll
    for (int i = 0; i < 17; i++) sm[t + i * 128] = __ldg(gx + t + i * 128);
    __syncthreads();

    int row = blockIdx.x * 128 + t;
    int n = row >> 10;
    int c = row & 1023;
    float s1[8] = {0, 0, 0, 0, 0, 0, 0, 0};
    float s2[8] = {0, 0, 0, 0, 0, 0, 0, 0};
    acc_loop_s<0>(sm + t * 17, s1, s2);

    float4* o1 = (float4*)(g_S1 + (size_t)row * 8);
    o1[0] = make_float4(s1[0], s1[1], s1[2], s1[3]);
    o1[1] = make_float4(s1[4], s1[5], s1[6], 0.f);
    float4* o2 = (float4*)(g_S2 + (size_t)row * 8);
    o2[0] = make_float4(s2[0], s2[1], s2[2], s2[3]);
    o2[1] = make_float4(s2[4], s2[5], s2[6], 0.f);
    // transposed mean-pooled layout for the GEMM: g_X[c][n*8+p]
    float4* gxo = (float4*)(g_X + (size_t)c * NP + n * 8);
    gxo[0] = make_float4(s1[0] * (1.f / 17.f), s1[1] * (1.f / 5.f),
                         s1[2] * (1.f / 5.f),  s1[3] * (1.f / 9.f));
    gxo[1] = make_float4(s1[4] * (1.f / 6.f),  s1[5] * (1.f / 6.f),
                         s1[6] * (1.f / 20.f), 0.f);
}

// ---------------- kB: tiled SGEMM h = Wt^T * X + pooled epilogue -----------
// grid (128, 2): bx = np-tile (32 np), by = o-half (128 o). 128 threads.
// Thread (tx = t&15 -> 8 o as 4 o-pairs, ty = t>>4 -> 4 np).
#define FMA2(A, X, W) \
    asm("fma.rn.f32x2 %0, %1, %2, %0;" : "+l"(A) : "l"(X), "l"(W))

__global__ void __launch_bounds__(128) kB(const float* __restrict__ b1) {
    __shared__ float Ws[2][32][128];      // 32 KB
    __shared__ float Xs[2][32][32];       //  8 KB
    int t = threadIdx.x;
    int bx = blockIdx.x;                  // np tile (32 wide)
    int by = blockIdx.y;                  // o half (128 wide)
    int tx = t & 15, ty = t >> 4;

    unsigned w_base = (unsigned)__cvta_generic_to_shared(Ws);
    unsigned x_base = (unsigned)__cvta_generic_to_shared(Xs);
    const float* gW = g_Wt + by * 128;
    const float* gX = g_X + bx * 32;

    auto load_chunk = [&](int k, int buf) {
#pragma unroll
        for (int i = 0; i < 8; i++) {          // W: 1024 float4
            int idx = t + i * 128;
            int cr = idx >> 5, c4 = idx & 31;
            const float* src = gW + (size_t)(k * 32 + cr) * OB + c4 * 4;
            unsigned dst = w_base + ((buf * 32 + cr) * 128 + c4 * 4) * 4;
            asm volatile("cp.async.cg.shared.global [%0], [%1], 16;"
                         :: "r"(dst), "l"(src));
        }
#pragma unroll
        for (int i = 0; i < 2; i++) {          // X: 256 float4
            int idx = t + i * 128;
            int cr = idx >> 3, c4 = idx & 7;
            const float* src = gX + (size_t)(k * 32 + cr) * NP + c4 * 4;
            unsigned dst = x_base + ((buf * 32 + cr) * 32 + c4 * 4) * 4;
            asm volatile("cp.async.cg.shared.global [%0], [%1], 16;"
                         :: "r"(dst), "l"(src));
        }
        asm volatile("cp.async.commit_group;");
    };

    unsigned long long acc[4][4];
#pragma unroll
    for (int i = 0; i < 4; i++)
#pragma unroll
        for (int j = 0; j < 4; j++) acc[i][j] = 0ULL;

    load_chunk(0, 0);
    for (int k = 0; k < 32; k++) {
        int buf = k & 1;
        if (k < 31) {
            load_chunk(k + 1, buf ^ 1);
            asm volatile("cp.async.wait_group 1;");
        } else {
            asm volatile("cp.async.wait_group 0;");
        }
        __syncthreads();

#pragma unroll 8
        for (int c = 0; c < 32; c++) {
            // W arrives as native o-pairs (u64) — no dup movs for W
            const ulonglong2* wr =
                (const ulonglong2*)&Ws[buf][c][tx * 8];
            ulonglong2 wA = wr[0];          // o-pairs 0,1
            ulonglong2 wB = wr[1];          // o-pairs 2,3
            float4 xv = *(const float4*)&Xs[buf][c][ty * 4];
            unsigned long long xd0, xd1, xd2, xd3;
            asm("mov.b64 %0, {%1,%1};" : "=l"(xd0) : "f"(xv.x));
            asm("mov.b64 %0, {%1,%1};" : "=l"(xd1) : "f"(xv.y));
            asm("mov.b64 %0, {%1,%1};" : "=l"(xd2) : "f"(xv.z));
            asm("mov.b64 %0, {%1,%1};" : "=l"(xd3) : "f"(xv.w));
            FMA2(acc[0][0], wA.x, xd0); FMA2(acc[0][1], wA.x, xd1);
            FMA2(acc[0][2], wA.x, xd2); FMA2(acc[0][3], wA.x, xd3);
            FMA2(acc[1][0], wA.y, xd0); FMA2(acc[1][1], wA.y, xd1);
            FMA2(acc[1][2], wA.y, xd2); FMA2(acc[1][3], wA.y, xd3);
            FMA2(acc[2][0], wB.x, xd0); FMA2(acc[2][1], wB.x, xd1);
            FMA2(acc[2][2], wB.x, xd2); FMA2(acc[2][3], wB.x, xd3);
            FMA2(acc[3][0], wB.y, xd0); FMA2(acc[3][1], wB.y, xd1);
            FMA2(acc[3][2], wB.y, xd2); FMA2(acc[3][3], wB.y, xd3);
        }
        __syncthreads();
    }

    // ---- epilogue: bias, per-np sum & max over this half's 128 o ----
    float bs[8];
#pragma unroll
    for (int i = 0; i < 8; i++) bs[i] = __ldg(b1 + by * 128 + tx * 8 + i);

    float s[4], mx[4];
#pragma unroll
    for (int j = 0; j < 4; j++) { s[j] = 0.f; mx[j] = -3.402823e38f; }
#pragma unroll
    for (int op = 0; op < 4; op++) {
#pragma unroll
        for (int j = 0; j < 4; j++) {
            float lo, hi;
            asm("mov.b64 {%0,%1}, %2;" : "=f"(lo), "=f"(hi) : "l"(acc[op][j]));
            lo += bs[2 * op]; hi += bs[2 * op + 1];
            s[j] += lo + hi;
            mx[j] = fmaxf(mx[j], fmaxf(lo, hi));
        }
    }
    // reduce across the 16 o-threads (xor within half-warp)
#pragma unroll
    for (int off = 8; off > 0; off >>= 1) {
#pragma unroll
        for (int j = 0; j < 4; j++) {
            s[j]  += __shfl_xor_sync(0xffffffffu, s[j], off);
            mx[j] = fmaxf(mx[j], __shfl_xor_sync(0xffffffffu, mx[j], off));
        }
    }
    if (tx == 0) {
        int npb = bx * 32 + ty * 4;
#pragma unroll
        for (int j = 0; j < 4; j++)
            g_pool[by * NP + npb + j] = make_float2(s[j], mx[j]);
    }
}

// ---------------- kC: softmax att (fused) + per-channel BN sums -------------
// grid (4, 32): x -> channel chunk (256 ch), y -> n chunk (16)
__global__ void __launch_bounds__(256) kC(const float* __restrict__ w2,
                                          const float* __restrict__ b2c) {
    __shared__ float sa[16][8];
    __shared__ float sa2[16][8];
    int c = blockIdx.x * 256 + threadIdx.x;
    int n0 = blockIdx.y * 16;

    if (threadIdx.x < 16) {
        int n = n0 + threadIdx.x;
        float w2a = __ldg(w2), w2b = __ldg(w2 + 1), bb = __ldg(b2c);
        float lg[PB];
        float mxv = -3.402823e38f;
#pragma unroll
        for (int p = 0; p < PB; p++) {
            float2 a0 = g_pool[n * 8 + p];
            float2 a1 = g_pool[NP + n * 8 + p];
            lg[p] = fmaf(w2a, (a0.x + a1.x) * (1.f / 256.f),
                         fmaf(w2b, fmaxf(a0.y, a1.y), bb));
            mxv = fmaxf(mxv, lg[p]);
        }
        float e[PB], ss = 0.f;
#pragma unroll
        for (int p = 0; p < PB; p++) { e[p] = expf(lg[p] - mxv); ss += e[p]; }
        float inv = 1.f / ss;
#pragma unroll
        for (int p = 0; p < PB; p++) {
            float a = e[p] * inv;
            sa[threadIdx.x][p] = a;
            sa2[threadIdx.x][p] = a * a;
            if (blockIdx.x == 0) g_att[n * 8 + p] = a;
        }
        sa[threadIdx.x][7] = 0.f;
        sa2[threadIdx.x][7] = 0.f;
        if (blockIdx.x == 0) g_att[n * 8 + 7] = 0.f;
    }
    __syncthreads();

    float sY = 0.f, sY2 = 0.f;
#pragma unroll 4
    for (int nn = 0; nn < 16; nn++) {
        size_t base = ((size_t)(n0 + nn) * CB + c) * 8;
        const float4* p1 = (const float4*)(g_S1 + base);
        const float4* p2 = (const float4*)(g_S2 + base);
        float4 q0 = __ldg(p1), q1 = __ldg(p1 + 1);
        float4 r0 = __ldg(p2), r1 = __ldg(p2 + 1);
        const float* a  = sa[nn];
        const float* a2 = sa2[nn];
        sY  = fmaf(q0.x, a[0], fmaf(q0.y, a[1], fmaf(q0.z, a[2], fmaf(q0.w, a[3],
              fmaf(q1.x, a[4], fmaf(q1.y, a[5], fmaf(q1.z, a[6], sY)))))));
        sY2 = fmaf(r0.x, a2[0], fmaf(r0.y, a2[1], fmaf(r0.z, a2[2], fmaf(r0.w, a2[3],
              fmaf(r1.x, a2[4], fmaf(r1.y, a2[5], fmaf(r1.z, a2[6], sY2)))))));
    }
    size_t oidx = ((size_t)blockIdx.y * CB + c) * 2;
    g_part[oidx]     = sY;
    g_part[oidx + 1] = sY2;
}

// ---------------- kC2: reduce partials -> scale/shift -----------------------
__global__ void __launch_bounds__(256) kC2(const float* __restrict__ gamma,
                                           const float* __restrict__ beta) {
    int c = blockIdx.x * 256 + threadIdx.x;
    float sY = 0.f, sY2 = 0.f;
#pragma unroll
    for (int w = 0; w < 32; w++) {
        sY  += g_part[(w * CB + c) * 2];
        sY2 += g_part[(w * CB + c) * 2 + 1];
    }
    const float inv = 1.f / (512.f * 68.f);
    float mean = sY * inv;
    float var = fmaf(-mean, mean, sY2 * inv);
    float sc = gamma[c] * rsqrtf(var + 1e-5f);
    g_scale[c] = sc;
    g_shift[c] = fmaf(-mean, sc, beta[c]);
}

// ---------------- kD: fused scale+BN+residual+ReLU (smem-staged) ------------
__global__ void __launch_bounds__(128) kD(const float* __restrict__ x,
                                          float* __restrict__ out) {
    __shared__ float4 sm[128 * 17];        // 34.8 KB
    int t = threadIdx.x;
    size_t base = (size_t)blockIdx.x * (128 * 17);
    const float4* gx = (const float4*)x + base;
    float4* go = (float4*)out + base;
#pragma unroll
    for (int i = 0; i < 17; i++) sm[t + i * 128] = __ldg(gx + t + i * 128);
    __syncthreads();

    int row = blockIdx.x * 128 + t;
    int n = row >> 10;
    int c = row & 1023;
    float sc = g_scale[c];
    float sh = g_shift[c];
    const float* at = g_att + n * 8;
    float m[PB];
#pragma unroll
    for (int p = 0; p < PB; p++) m[p] = fmaf(__ldg(at + p), sc, 1.f);
    d_loop_s<0>(sm + t * 17, m, sh);
    __syncthreads();
#pragma unroll
    for (int i = 0; i < 17; i++) go[t + i * 128] = sm[t + i * 128];
}

// ---------------- launch ----------------------------------------------------
extern "C" void kernel_launch(void* const* d_in, const int* in_sizes, int n_in,
                              void* d_out, int out_size) {
    const float* x     = (const float*)d_in[0];  // (512,1024,1,68)
    const float* w1    = (const float*)d_in[1];  // (256,1024)
    const float* b1    = (const float*)d_in[2];  // (256,)
    const float* w2    = (const float*)d_in[3];  // (2,)
    const float* b2    = (const float*)d_in[4];  // scalar
    const float* gamma = (const float*)d_in[5];  // (1024,)
    const float* beta  = (const float*)d_in[6];  // (1024,)
    float* out = (float*)d_out;

    kAT<<<4096 + 2048, 128>>>(x, w1);
    kB<<<dim3(128, 2), 128>>>(b1);
    kC<<<dim3(4, 32), 256>>>(w2, b2);
    kC2<<<4, 256>>>(gamma, beta);
    kD<<<4096, 128>>>(x, out);
}

// round 10
// speedup vs baseline: 2.4034x; 1.2970x over previous
#include <cuda_runtime.h>
#include <cstdint>

#define NB   512
#define CB   1024
#define VB   68
#define PB   7
#define OB   256   // C/4
#define NP   4096  // NB * 8 (p padded to 8)
#define WPAD 264   // 256 + 8  -> bank-bijective fragment loads
#define XPAD 40    // 32 + 8

// ---------------- scratch (device globals; no allocation allowed) ----------
__device__ float  g_S1[NB * CB * 8];    // part-wise sums of x,  padded P->8
__device__ float  g_S2[NB * CB * 8];    // part-wise sums of x^2
__device__ float  g_X [CB * NP];        // mean-pooled x_parts (tf32), [c][np]
__device__ float  g_Wt[CB * OB];        // transposed conv1 weight (tf32): [c][o]
__device__ float2 g_pool[NP];           // per np: (sum, max) over all 256 o
__device__ float  g_att[NB * 8];        // softmax attention per (n, p), padded
__device__ float  g_part[32 * CB * 2];  // partial BN sums (32 n-chunks)
__device__ float  g_scale[CB];
__device__ float  g_shift[CB];

__device__ __forceinline__ float tf32r(float x) {
    unsigned u;
    asm("cvt.rna.tf32.f32 %0, %1;" : "=r"(u) : "f"(x));
    return __uint_as_float(u);
}

// ---------------- compile-time joint -> part mapping -----------------------
__device__ __host__ __forceinline__ constexpr int part_of(int v) {
    return v < 17 ? 0 : v < 22 ? 1 : v < 27 ? 2 : v < 36 ? 3 :
           v < 42 ? 4 : v < 48 ? 5 : 6;
}

template <int VV>
__device__ __forceinline__ void acc_one(float val, float* s1, float* s2) {
    constexpr int j = part_of(VV);
    s1[j] += val;
    s2[j] = fmaf(val, val, s2[j]);
}

template <int I>
__device__ __forceinline__ void acc_loop_s(const float4* xr, float* s1, float* s2) {
    if constexpr (I < 17) {
        float4 q = xr[I];
        acc_one<4 * I + 0>(q.x, s1, s2);
        acc_one<4 * I + 1>(q.y, s1, s2);
        acc_one<4 * I + 2>(q.z, s1, s2);
        acc_one<4 * I + 3>(q.w, s1, s2);
        acc_loop_s<I + 1>(xr, s1, s2);
    }
}

template <int I>
__device__ __forceinline__ void d_loop_s(float4* xr, const float* m, float sh) {
    if constexpr (I < 17) {
        float4 q = xr[I];
        constexpr int j0 = part_of(4 * I + 0);
        constexpr int j1 = part_of(4 * I + 1);
        constexpr int j2 = part_of(4 * I + 2);
        constexpr int j3 = part_of(4 * I + 3);
        q.x = fmaxf(fmaf(q.x, m[j0], sh), 0.f);
        q.y = fmaxf(fmaf(q.y, m[j1], sh), 0.f);
        q.z = fmaxf(fmaf(q.z, m[j2], sh), 0.f);
        q.w = fmaxf(fmaf(q.w, m[j3], sh), 0.f);
        xr[I] = q;
        d_loop_s<I + 1>(xr, m, sh);
    }
}

// ---------------- kAT: part sums (smem-staged) + W transpose (tf32) ---------
// blocks [0, 4096): part sums over 128 rows each; blocks [4096, 6144): kT.
__global__ void __launch_bounds__(128) kAT(const float* __restrict__ x,
                                           const float* __restrict__ w1) {
    int t = threadIdx.x;
    if (blockIdx.x >= 4096) {              // ---- transpose conv1_w, tf32 ----
        int idx = (blockIdx.x - 4096) * 128 + t;   // 0 .. 262143
        int o = idx >> 10;
        int c = idx & 1023;
        g_Wt[c * OB + o] = tf32r(w1[idx]);
        return;
    }
    __shared__ float4 sm[128 * 17];        // 128 rows x 68 floats = 34.8 KB
    const float4* gx = (const float4*)x + (size_t)blockIdx.x * (128 * 17);
#pragma unroll
    for (int i = 0; i < 17; i++) sm[t + i * 128] = __ldg(gx + t + i * 128);
    __syncthreads();

    int row = blockIdx.x * 128 + t;
    int n = row >> 10;
    int c = row & 1023;
    float s1[8] = {0, 0, 0, 0, 0, 0, 0, 0};
    float s2[8] = {0, 0, 0, 0, 0, 0, 0, 0};
    acc_loop_s<0>(sm + t * 17, s1, s2);

    float4* o1 = (float4*)(g_S1 + (size_t)row * 8);
    o1[0] = make_float4(s1[0], s1[1], s1[2], s1[3]);
    o1[1] = make_float4(s1[4], s1[5], s1[6], 0.f);
    float4* o2 = (float4*)(g_S2 + (size_t)row * 8);
    o2[0] = make_float4(s2[0], s2[1], s2[2], s2[3]);
    o2[1] = make_float4(s2[4], s2[5], s2[6], 0.f);
    // transposed mean-pooled layout for the MMA (pre-rounded to tf32).
    // NOTE: the mean normalization 1/count[p] is applied HERE and only here.
    float4* gxo = (float4*)(g_X + (size_t)c * NP + n * 8);
    gxo[0] = make_float4(tf32r(s1[0] * (1.f / 17.f)), tf32r(s1[1] * (1.f / 5.f)),
                         tf32r(s1[2] * (1.f / 5.f)),  tf32r(s1[3] * (1.f / 9.f)));
    gxo[1] = make_float4(tf32r(s1[4] * (1.f / 6.f)),  tf32r(s1[5] * (1.f / 6.f)),
                         tf32r(s1[6] * (1.f / 20.f)), 0.f);
}

// ---------------- kB: tf32 tensor-core GEMM + pooled epilogue ---------------
// grid 128: bx = np-tile (32 np). 256 threads = 8 warps; full o=256 per block.
// Warp w -> m-tiles {2w, 2w+1} (32 o), all 4 n-tiles. k-chunk = 16 c.
__global__ void __launch_bounds__(256) kB(const float* __restrict__ b1) {
    __shared__ float Ws[2][16][WPAD];     // ~33.8 KB
    __shared__ float Xs[2][16][XPAD];     //  ~5.1 KB
    __shared__ float2 red[8][32];
    int t = threadIdx.x;
    int bx = blockIdx.x;
    int w = t >> 5, lane = t & 31;
    int lq = lane >> 2, lr = lane & 3;

    unsigned wb0 = (unsigned)__cvta_generic_to_shared(&Ws[0][0][0]);
    unsigned xb0 = (unsigned)__cvta_generic_to_shared(&Xs[0][0][0]);

    auto load_chunk = [&](int k, int buf) {
        const float* srcW = g_Wt + (size_t)(k * 16) * OB;
        unsigned wb = wb0 + buf * (16 * WPAD * 4);
#pragma unroll
        for (int i = 0; i < 4; i++) {
            int idx = t + i * 256;             // 0..1023
            int cr = idx >> 6, o4 = idx & 63;
            unsigned dst = wb + (cr * WPAD + o4 * 4) * 4;
            asm volatile("cp.async.cg.shared.global [%0], [%1], 16;"
                         :: "r"(dst), "l"(srcW + cr * OB + o4 * 4));
        }
        if (t < 128) {
            int cr = t >> 3, n4 = t & 7;
            unsigned dst = xb0 + buf * (16 * XPAD * 4) + (cr * XPAD + n4 * 4) * 4;
            asm volatile("cp.async.cg.shared.global [%0], [%1], 16;"
                :: "r"(dst), "l"(g_X + (size_t)(k * 16 + cr) * NP + bx * 32 + n4 * 4));
        }
        asm volatile("cp.async.commit_group;");
    };

    float acc[2][4][4];
#pragma unroll
    for (int a = 0; a < 2; a++)
#pragma unroll
        for (int b = 0; b < 4; b++)
#pragma unroll
            for (int r = 0; r < 4; r++) acc[a][b][r] = 0.f;

    load_chunk(0, 0);
    for (int k = 0; k < 64; k++) {
        int buf = k & 1;
        if (k < 63) {
            load_chunk(k + 1, buf ^ 1);
            asm volatile("cp.async.wait_group 1;");
        } else {
            asm volatile("cp.async.wait_group 0;");
        }
        __syncthreads();

#pragma unroll
        for (int s = 0; s < 2; s++) {
            int kl = s * 8;
            unsigned bf[4][2];
#pragma unroll
            for (int nt = 0; nt < 4; nt++) {
                bf[nt][0] = __float_as_uint(Xs[buf][kl + lr][nt * 8 + lq]);
                bf[nt][1] = __float_as_uint(Xs[buf][kl + lr + 4][nt * 8 + lq]);
            }
#pragma unroll
            for (int mi = 0; mi < 2; mi++) {
                int ob = (w * 2 + mi) * 16 + lq;
                unsigned a0 = __float_as_uint(Ws[buf][kl + lr][ob]);
                unsigned a1 = __float_as_uint(Ws[buf][kl + lr][ob + 8]);
                unsigned a2 = __float_as_uint(Ws[buf][kl + lr + 4][ob]);
                unsigned a3 = __float_as_uint(Ws[buf][kl + lr + 4][ob + 8]);
#pragma unroll
                for (int nt = 0; nt < 4; nt++) {
                    asm("mma.sync.aligned.m16n8k8.row.col.f32.tf32.tf32.f32 "
                        "{%0,%1,%2,%3}, {%4,%5,%6,%7}, {%8,%9}, {%0,%1,%2,%3};"
                        : "+f"(acc[mi][nt][0]), "+f"(acc[mi][nt][1]),
                          "+f"(acc[mi][nt][2]), "+f"(acc[mi][nt][3])
                        : "r"(a0), "r"(a1), "r"(a2), "r"(a3),
                          "r"(bf[nt][0]), "r"(bf[nt][1]));
                }
            }
        }
        __syncthreads();
    }

    // ---- epilogue: bias, per-np sum & max over all o (g_X already means) ----
    float br0 = __ldg(b1 + w * 32 + lq);
    float br1 = __ldg(b1 + w * 32 + lq + 8);
    float br2 = __ldg(b1 + w * 32 + 16 + lq);
    float br3 = __ldg(b1 + w * 32 + 16 + lq + 8);

#pragma unroll
    for (int nt = 0; nt < 4; nt++) {
        float he0 = acc[0][nt][0] + br0;   // (o = w*32+lq,    np col 2*lr)
        float ho0 = acc[0][nt][1] + br0;   // (                np col 2*lr+1)
        float he1 = acc[0][nt][2] + br1;   // (o = w*32+lq+8)
        float ho1 = acc[0][nt][3] + br1;
        float he2 = acc[1][nt][0] + br2;   // (o = w*32+16+lq)
        float ho2 = acc[1][nt][1] + br2;
        float he3 = acc[1][nt][2] + br3;   // (o = w*32+24+lq)
        float ho3 = acc[1][nt][3] + br3;
        float se = he0 + he1 + he2 + he3;
        float so = ho0 + ho1 + ho2 + ho3;
        float me = fmaxf(fmaxf(he0, he1), fmaxf(he2, he3));
        float mo = fmaxf(fmaxf(ho0, ho1), fmaxf(ho2, ho3));
#pragma unroll
        for (int off = 4; off < 32; off <<= 1) {
            se += __shfl_xor_sync(0xffffffffu, se, off);
            so += __shfl_xor_sync(0xffffffffu, so, off);
            me = fmaxf(me, __shfl_xor_sync(0xffffffffu, me, off));
            mo = fmaxf(mo, __shfl_xor_sync(0xffffffffu, mo, off));
        }
        if (lq == 0) {
            red[w][nt * 8 + 2 * lr]     = make_float2(se, me);
            red[w][nt * 8 + 2 * lr + 1] = make_float2(so, mo);
        }
    }
    __syncthreads();
    if (t < 32) {
        float s = 0.f, m = -3.402823e38f;
#pragma unroll
        for (int ww = 0; ww < 8; ww++) {
            float2 v = red[ww][t];
            s += v.x;
            m = fmaxf(m, v.y);
        }
        g_pool[bx * 32 + t] = make_float2(s, m);
    }
}

// ---------------- kC: softmax att (fused) + per-channel BN sums -------------
// grid (4, 32): x -> channel chunk (256 ch), y -> n chunk (16)
__global__ void __launch_bounds__(256) kC(const float* __restrict__ w2,
                                          const float* __restrict__ b2c) {
    __shared__ float sa[16][8];
    __shared__ float sa2[16][8];
    int c = blockIdx.x * 256 + threadIdx.x;
    int n0 = blockIdx.y * 16;

    if (threadIdx.x < 16) {
        int n = n0 + threadIdx.x;
        float w2a = __ldg(w2), w2b = __ldg(w2 + 1), bb = __ldg(b2c);
        float lg[PB];
        float mxv = -3.402823e38f;
#pragma unroll
        for (int p = 0; p < PB; p++) {
            float2 a0 = g_pool[n * 8 + p];
            lg[p] = fmaf(w2a, a0.x * (1.f / 256.f), fmaf(w2b, a0.y, bb));
            mxv = fmaxf(mxv, lg[p]);
        }
        float e[PB], ss = 0.f;
#pragma unroll
        for (int p = 0; p < PB; p++) { e[p] = expf(lg[p] - mxv); ss += e[p]; }
        float inv = 1.f / ss;
#pragma unroll
        for (int p = 0; p < PB; p++) {
            float a = e[p] * inv;
            sa[threadIdx.x][p] = a;
            sa2[threadIdx.x][p] = a * a;
            if (blockIdx.x == 0) g_att[n * 8 + p] = a;
        }
        sa[threadIdx.x][7] = 0.f;
        sa2[threadIdx.x][7] = 0.f;
        if (blockIdx.x == 0) g_att[n * 8 + 7] = 0.f;
    }
    __syncthreads();

    float sY = 0.f, sY2 = 0.f;
#pragma unroll 4
    for (int nn = 0; nn < 16; nn++) {
        size_t base = ((size_t)(n0 + nn) * CB + c) * 8;
        const float4* p1 = (const float4*)(g_S1 + base);
        const float4* p2 = (const float4*)(g_S2 + base);
        float4 q0 = __ldg(p1), q1 = __ldg(p1 + 1);
        float4 r0 = __ldg(p2), r1 = __ldg(p2 + 1);
        const float* a  = sa[nn];
        const float* a2 = sa2[nn];
        sY  = fmaf(q0.x, a[0], fmaf(q0.y, a[1], fmaf(q0.z, a[2], fmaf(q0.w, a[3],
              fmaf(q1.x, a[4], fmaf(q1.y, a[5], fmaf(q1.z, a[6], sY)))))));
        sY2 = fmaf(r0.x, a2[0], fmaf(r0.y, a2[1], fmaf(r0.z, a2[2], fmaf(r0.w, a2[3],
              fmaf(r1.x, a2[4], fmaf(r1.y, a2[5], fmaf(r1.z, a2[6], sY2)))))));
    }
    size_t oidx = ((size_t)blockIdx.y * CB + c) * 2;
    g_part[oidx]     = sY;
    g_part[oidx + 1] = sY2;
}

// ---------------- kC2: warp-per-channel partial reduce -> scale/shift -------
__global__ void __launch_bounds__(256) kC2(const float* __restrict__ gamma,
                                           const float* __restrict__ beta) {
    int w = threadIdx.x >> 5, lane = threadIdx.x & 31;
    int c = blockIdx.x * 8 + w;
    float2 v = *(const float2*)(g_part + ((size_t)lane * CB + c) * 2);
    float sY = v.x, sY2 = v.y;
#pragma unroll
    for (int off = 16; off > 0; off >>= 1) {
        sY  += __shfl_xor_sync(0xffffffffu, sY, off);
        sY2 += __shfl_xor_sync(0xffffffffu, sY2, off);
    }
    if (lane == 0) {
        const float inv = 1.f / (512.f * 68.f);
        float mean = sY * inv;
        float var = fmaf(-mean, mean, sY2 * inv);
        float sc = gamma[c] * rsqrtf(var + 1e-5f);
        g_scale[c] = sc;
        g_shift[c] = fmaf(-mean, sc, beta[c]);
    }
}

// ---------------- kD: fused scale+BN+residual+ReLU (smem-staged) ------------
__global__ void __launch_bounds__(128) kD(const float* __restrict__ x,
                                          float* __restrict__ out) {
    __shared__ float4 sm[128 * 17];        // 34.8 KB
    int t = threadIdx.x;
    size_t base = (size_t)blockIdx.x * (128 * 17);
    const float4* gx = (const float4*)x + base;
    float4* go = (float4*)out + base;
#pragma unroll
    for (int i = 0; i < 17; i++) sm[t + i * 128] = __ldg(gx + t + i * 128);
    __syncthreads();

    int row = blockIdx.x * 128 + t;
    int n = row >> 10;
    int c = row & 1023;
    float sc = g_scale[c];
    float sh = g_shift[c];
    const float* at = g_att + n * 8;
    float m[PB];
#pragma unroll
    for (int p = 0; p < PB; p++) m[p] = fmaf(__ldg(at + p), sc, 1.f);
    d_loop_s<0>(sm + t * 17, m, sh);
    __syncthreads();
#pragma unroll
    for (int i = 0; i < 17; i++) go[t + i * 128] = sm[t + i * 128];
}

// ---------------- launch ----------------------------------------------------
extern "C" void kernel_launch(void* const* d_in, const int* in_sizes, int n_in,
                              void* d_out, int out_size) {
    const float* x     = (const float*)d_in[0];  // (512,1024,1,68)
    const float* w1    = (const float*)d_in[1];  // (256,1024)
    const float* b1    = (const float*)d_in[2];  // (256,)
    const float* w2    = (const float*)d_in[3];  // (2,)
    const float* b2    = (const float*)d_in[4];  // scalar
    const float* gamma = (const float*)d_in[5];  // (1024,)
    const float* beta  = (const float*)d_in[6];  // (1024,)
    float* out = (float*)d_out;

    kAT<<<4096 + 2048, 128>>>(x, w1);
    kB<<<128, 256>>>(b1);
    kC<<<dim3(4, 32), 256>>>(w2, b2);
    kC2<<<128, 256>>>(gamma, beta);
    kD<<<4096, 128>>>(x, out);
}

// round 12
// speedup vs baseline: 2.5799x; 1.0735x over previous
#include <cuda_runtime.h>
#include <cstdint>

#define NB   512
#define CB   1024
#define VB   68
#define PB   7
#define OB   256   // C/4
#define NP   4096  // NB * 8 (p padded to 8)
#define WPAD 264   // 256 + 8  -> bank-bijective fragment loads
#define XPAD 40    // 32 + 8

// ---------------- scratch (device globals; no allocation allowed) ----------
__device__ float  g_S2[NB * CB * 8];    // part-wise sums of x^2
__device__ float  g_X [CB * NP];        // mean-pooled x_parts (tf32), [c][np]
__device__ float  g_Wt[CB * OB];        // transposed conv1 weight (tf32): [c][o]
__device__ float2 g_pool[NP];           // per np: (sum, max) over all 256 o
__device__ float  g_att[NB * 8];        // softmax attention per (n, p), padded
__device__ float  g_part[32 * CB * 2];  // partial BN sums (32 n-chunks)
__device__ float  g_scale[CB];
__device__ float  g_shift[CB];
__device__ int    g_cnt[4];             // last-block counters (zero at init,
                                        // reset after each use -> graph-safe)

__device__ __forceinline__ float tf32r(float x) {
    unsigned u;
    asm("cvt.rna.tf32.f32 %0, %1;" : "=r"(u) : "f"(x));
    return __uint_as_float(u);
}

// ---------------- compile-time joint -> part mapping -----------------------
__device__ __host__ __forceinline__ constexpr int part_of(int v) {
    return v < 17 ? 0 : v < 22 ? 1 : v < 27 ? 2 : v < 36 ? 3 :
           v < 42 ? 4 : v < 48 ? 5 : 6;
}

template <int VV>
__device__ __forceinline__ void acc_one(float val, float* s1, float* s2) {
    constexpr int j = part_of(VV);
    s1[j] += val;
    s2[j] = fmaf(val, val, s2[j]);
}

template <int I>
__device__ __forceinline__ void acc_loop_s(const float4* xr, float* s1, float* s2) {
    if constexpr (I < 17) {
        float4 q = xr[I];
        acc_one<4 * I + 0>(q.x, s1, s2);
        acc_one<4 * I + 1>(q.y, s1, s2);
        acc_one<4 * I + 2>(q.z, s1, s2);
        acc_one<4 * I + 3>(q.w, s1, s2);
        acc_loop_s<I + 1>(xr, s1, s2);
    }
}

template <int I>
__device__ __forceinline__ void d_loop_s(float4* xr, const float* m, float sh) {
    if constexpr (I < 17) {
        float4 q = xr[I];
        constexpr int j0 = part_of(4 * I + 0);
        constexpr int j1 = part_of(4 * I + 1);
        constexpr int j2 = part_of(4 * I + 2);
        constexpr int j3 = part_of(4 * I + 3);
        q.x = fmaxf(fmaf(q.x, m[j0], sh), 0.f);
        q.y = fmaxf(fmaf(q.y, m[j1], sh), 0.f);
        q.z = fmaxf(fmaf(q.z, m[j2], sh), 0.f);
        q.w = fmaxf(fmaf(q.w, m[j3], sh), 0.f);
        xr[I] = q;
        d_loop_s<I + 1>(xr, m, sh);
    }
}

// ---------------- kAT: part sums (smem-staged) + W transpose (tf32) ---------
// blocks [0, 4096): part sums over 128 rows each; blocks [4096, 6144): kT.
__global__ void __launch_bounds__(128) kAT(const float* __restrict__ x,
                                           const float* __restrict__ w1) {
    int t = threadIdx.x;
    if (blockIdx.x >= 4096) {              // ---- transpose conv1_w, tf32 ----
        int idx = (blockIdx.x - 4096) * 128 + t;   // 0 .. 262143
        int o = idx >> 10;
        int c = idx & 1023;
        g_Wt[c * OB + o] = tf32r(w1[idx]);
        return;
    }
    __shared__ float4 sm[128 * 17];        // 128 rows x 68 floats = 34.8 KB
    const float4* gx = (const float4*)x + (size_t)blockIdx.x * (128 * 17);
#pragma unroll
    for (int i = 0; i < 17; i++) sm[t + i * 128] = __ldg(gx + t + i * 128);
    __syncthreads();

    int row = blockIdx.x * 128 + t;
    int n = row >> 10;
    int c = row & 1023;
    float s1[8] = {0, 0, 0, 0, 0, 0, 0, 0};
    float s2[8] = {0, 0, 0, 0, 0, 0, 0, 0};
    acc_loop_s<0>(sm + t * 17, s1, s2);

    float4* o2 = (float4*)(g_S2 + (size_t)row * 8);
    o2[0] = make_float4(s2[0], s2[1], s2[2], s2[3]);
    o2[1] = make_float4(s2[4], s2[5], s2[6], 0.f);
    // transposed mean-pooled layout (tf32). Mean 1/count[p] applied HERE only.
    float4* gxo = (float4*)(g_X + (size_t)c * NP + n * 8);
    gxo[0] = make_float4(tf32r(s1[0] * (1.f / 17.f)), tf32r(s1[1] * (1.f / 5.f)),
                         tf32r(s1[2] * (1.f / 5.f)),  tf32r(s1[3] * (1.f / 9.f)));
    gxo[1] = make_float4(tf32r(s1[4] * (1.f / 6.f)),  tf32r(s1[5] * (1.f / 6.f)),
                         tf32r(s1[6] * (1.f / 20.f)), 0.f);
}

// ---------------- kB: tf32 tensor-core GEMM + pooled epilogue ---------------
// grid 128: bx = np-tile (32 np). 256 threads = 8 warps; full o=256 per block.
__global__ void __launch_bounds__(256) kB(const float* __restrict__ b1) {
    __shared__ float Ws[2][16][WPAD];     // ~33.8 KB
    __shared__ float Xs[2][16][XPAD];     //  ~5.1 KB
    __shared__ float2 red[8][32];
    int t = threadIdx.x;
    int bx = blockIdx.x;
    int w = t >> 5, lane = t & 31;
    int lq = lane >> 2, lr = lane & 3;

    unsigned wb0 = (unsigned)__cvta_generic_to_shared(&Ws[0][0][0]);
    unsigned xb0 = (unsigned)__cvta_generic_to_shared(&Xs[0][0][0]);

    auto load_chunk = [&](int k, int buf) {
        const float* srcW = g_Wt + (size_t)(k * 16) * OB;
        unsigned wb = wb0 + buf * (16 * WPAD * 4);
#pragma unroll
        for (int i = 0; i < 4; i++) {
            int idx = t + i * 256;             // 0..1023
            int cr = idx >> 6, o4 = idx & 63;
            unsigned dst = wb + (cr * WPAD + o4 * 4) * 4;
            asm volatile("cp.async.cg.shared.global [%0], [%1], 16;"
                         :: "r"(dst), "l"(srcW + cr * OB + o4 * 4));
        }
        if (t < 128) {
            int cr = t >> 3, n4 = t & 7;
            unsigned dst = xb0 + buf * (16 * XPAD * 4) + (cr * XPAD + n4 * 4) * 4;
            asm volatile("cp.async.cg.shared.global [%0], [%1], 16;"
                :: "r"(dst), "l"(g_X + (size_t)(k * 16 + cr) * NP + bx * 32 + n4 * 4));
        }
        asm volatile("cp.async.commit_group;");
    };

    float acc[2][4][4];
#pragma unroll
    for (int a = 0; a < 2; a++)
#pragma unroll
        for (int b = 0; b < 4; b++)
#pragma unroll
            for (int r = 0; r < 4; r++) acc[a][b][r] = 0.f;

    load_chunk(0, 0);
    for (int k = 0; k < 64; k++) {
        int buf = k & 1;
        if (k < 63) {
            load_chunk(k + 1, buf ^ 1);
            asm volatile("cp.async.wait_group 1;");
        } else {
            asm volatile("cp.async.wait_group 0;");
        }
        __syncthreads();

#pragma unroll
        for (int s = 0; s < 2; s++) {
            int kl = s * 8;
            unsigned bf[4][2];
#pragma unroll
            for (int nt = 0; nt < 4; nt++) {
                bf[nt][0] = __float_as_uint(Xs[buf][kl + lr][nt * 8 + lq]);
                bf[nt][1] = __float_as_uint(Xs[buf][kl + lr + 4][nt * 8 + lq]);
            }
#pragma unroll
            for (int mi = 0; mi < 2; mi++) {
                int ob = (w * 2 + mi) * 16 + lq;
                unsigned a0 = __float_as_uint(Ws[buf][kl + lr][ob]);
                unsigned a1 = __float_as_uint(Ws[buf][kl + lr][ob + 8]);
                unsigned a2 = __float_as_uint(Ws[buf][kl + lr + 4][ob]);
                unsigned a3 = __float_as_uint(Ws[buf][kl + lr + 4][ob + 8]);
#pragma unroll
                for (int nt = 0; nt < 4; nt++) {
                    asm("mma.sync.aligned.m16n8k8.row.col.f32.tf32.tf32.f32 "
                        "{%0,%1,%2,%3}, {%4,%5,%6,%7}, {%8,%9}, {%0,%1,%2,%3};"
                        : "+f"(acc[mi][nt][0]), "+f"(acc[mi][nt][1]),
                          "+f"(acc[mi][nt][2]), "+f"(acc[mi][nt][3])
                        : "r"(a0), "r"(a1), "r"(a2), "r"(a3),
                          "r"(bf[nt][0]), "r"(bf[nt][1]));
                }
            }
        }
        __syncthreads();
    }

    // ---- epilogue: bias, per-np sum & max over all o (g_X already means) ----
    float br0 = __ldg(b1 + w * 32 + lq);
    float br1 = __ldg(b1 + w * 32 + lq + 8);
    float br2 = __ldg(b1 + w * 32 + 16 + lq);
    float br3 = __ldg(b1 + w * 32 + 16 + lq + 8);

#pragma unroll
    for (int nt = 0; nt < 4; nt++) {
        float he0 = acc[0][nt][0] + br0;
        float ho0 = acc[0][nt][1] + br0;
        float he1 = acc[0][nt][2] + br1;
        float ho1 = acc[0][nt][3] + br1;
        float he2 = acc[1][nt][0] + br2;
        float ho2 = acc[1][nt][1] + br2;
        float he3 = acc[1][nt][2] + br3;
        float ho3 = acc[1][nt][3] + br3;
        float se = he0 + he1 + he2 + he3;
        float so = ho0 + ho1 + ho2 + ho3;
        float me = fmaxf(fmaxf(he0, he1), fmaxf(he2, he3));
        float mo = fmaxf(fmaxf(ho0, ho1), fmaxf(ho2, ho3));
#pragma unroll
        for (int off = 4; off < 32; off <<= 1) {
            se += __shfl_xor_sync(0xffffffffu, se, off);
            so += __shfl_xor_sync(0xffffffffu, so, off);
            me = fmaxf(me, __shfl_xor_sync(0xffffffffu, me, off));
            mo = fmaxf(mo, __shfl_xor_sync(0xffffffffu, mo, off));
        }
        if (lq == 0) {
            red[w][nt * 8 + 2 * lr]     = make_float2(se, me);
            red[w][nt * 8 + 2 * lr + 1] = make_float2(so, mo);
        }
    }
    __syncthreads();
    if (t < 32) {
        float s = 0.f, m = -3.402823e38f;
#pragma unroll
        for (int ww = 0; ww < 8; ww++) {
            float2 v = red[ww][t];
            s += v.x;
            m = fmaxf(m, v.y);
        }
        g_pool[bx * 32 + t] = make_float2(s, m);
    }
}

// ---------------- kC: softmax + BN sums + fused last-block scale/shift ------
// grid (4, 32): x -> channel chunk (256 ch), y -> n chunk (16).
// The last block to finish per channel chunk also reduces the 32 partials.
__global__ void __launch_bounds__(256) kC(const float* __restrict__ w2,
                                          const float* __restrict__ b2c,
                                          const float* __restrict__ gamma,
                                          const float* __restrict__ beta) {
    __shared__ float sa[16][8];    // att * count[p]  (for mean sums over g_X)
    __shared__ float sa2[16][8];   // att^2           (for raw g_S2 sums)
    __shared__ int is_last;
    int c = blockIdx.x * 256 + threadIdx.x;
    int n0 = blockIdx.y * 16;

    if (threadIdx.x < 16) {
        int n = n0 + threadIdx.x;
        float w2a = __ldg(w2), w2b = __ldg(w2 + 1), bb = __ldg(b2c);
        float lg[PB];
        float mxv = -3.402823e38f;
#pragma unroll
        for (int p = 0; p < PB; p++) {
            float2 a0 = g_pool[n * 8 + p];
            lg[p] = fmaf(w2a, a0.x * (1.f / 256.f), fmaf(w2b, a0.y, bb));
            mxv = fmaxf(mxv, lg[p]);
        }
        float e[PB], ss = 0.f;
#pragma unroll
        for (int p = 0; p < PB; p++) { e[p] = expf(lg[p] - mxv); ss += e[p]; }
        float inv = 1.f / ss;
        const float cnt[7] = {17.f, 5.f, 5.f, 9.f, 6.f, 6.f, 20.f};
#pragma unroll
        for (int p = 0; p < PB; p++) {
            float a = e[p] * inv;
            sa[threadIdx.x][p] = a * cnt[p];
            sa2[threadIdx.x][p] = a * a;
            if (blockIdx.x == 0) g_att[n * 8 + p] = a;
        }
        sa[threadIdx.x][7] = 0.f;
        sa2[threadIdx.x][7] = 0.f;
        if (blockIdx.x == 0) g_att[n * 8 + 7] = 0.f;
    }
    __syncthreads();

    float sY = 0.f, sY2 = 0.f;
    const float4* px = (const float4*)(g_X + (size_t)c * NP + n0 * 8);
#pragma unroll 4
    for (int nn = 0; nn < 16; nn++) {
        float4 q0 = __ldg(px + nn * 2), q1 = __ldg(px + nn * 2 + 1);
        size_t b2s = ((size_t)(n0 + nn) * CB + c) * 8;
        const float4* p2 = (const float4*)(g_S2 + b2s);
        float4 r0 = __ldg(p2), r1 = __ldg(p2 + 1);
        const float* a  = sa[nn];
        const float* a2 = sa2[nn];
        sY  = fmaf(q0.x, a[0], fmaf(q0.y, a[1], fmaf(q0.z, a[2], fmaf(q0.w, a[3],
              fmaf(q1.x, a[4], fmaf(q1.y, a[5], fmaf(q1.z, a[6], sY)))))));
        sY2 = fmaf(r0.x, a2[0], fmaf(r0.y, a2[1], fmaf(r0.z, a2[2], fmaf(r0.w, a2[3],
              fmaf(r1.x, a2[4], fmaf(r1.y, a2[5], fmaf(r1.z, a2[6], sY2)))))));
    }
    size_t oidx = ((size_t)blockIdx.y * CB + c) * 2;
    g_part[oidx]     = sY;
    g_part[oidx + 1] = sY2;

    // ---- last-block reduction for this channel chunk ----
    __threadfence();
    if (threadIdx.x == 0)
        is_last = (atomicAdd(&g_cnt[blockIdx.x], 1) == 31);
    __syncthreads();
    if (is_last) {
        float tY = 0.f, tY2 = 0.f;
#pragma unroll
        for (int w = 0; w < 32; w++) {
            float2 v = __ldcg((const float2*)(g_part + ((size_t)w * CB + c) * 2));
            tY += v.x;
            tY2 += v.y;
        }
        const float inv = 1.f / (512.f * 68.f);
        float mean = tY * inv;
        float var = fmaf(-mean, mean, tY2 * inv);
        float sc = __ldg(gamma + c) * rsqrtf(var + 1e-5f);
        g_scale[c] = sc;
        g_shift[c] = fmaf(-mean, sc, __ldg(beta + c));
        if (threadIdx.x == 0) atomicExch(&g_cnt[blockIdx.x], 0);  // graph-safe
    }
}

// ---------------- kD: fused scale+BN+residual+ReLU (reverse order) ----------
__global__ void __launch_bounds__(128) kD(const float* __restrict__ x,
                                          float* __restrict__ out) {
    __shared__ float4 sm[128 * 17];        // 34.8 KB
    int t = threadIdx.x;
    int bid = 4095 - blockIdx.x;           // reverse: reuse x tail from L2
    size_t base = (size_t)bid * (128 * 17);
    const float4* gx = (const float4*)x + base;
    float4* go = (float4*)out + base;
#pragma unroll
    for (int i = 0; i < 17; i++) sm[t + i * 128] = __ldg(gx + t + i * 128);
    __syncthreads();

    int row = bid * 128 + t;
    int n = row >> 10;
    int c = row & 1023;
    float sc = g_scale[c];
    float sh = g_shift[c];
    const float* at = g_att + n * 8;
    float m[PB];
#pragma unroll
    for (int p = 0; p < PB; p++) m[p] = fmaf(__ldg(at + p), sc, 1.f);
    d_loop_s<0>(sm + t * 17, m, sh);
    __syncthreads();
#pragma unroll
    for (int i = 0; i < 17; i++) go[t + i * 128] = sm[t + i * 128];
}

// ---------------- launch ----------------------------------------------------
extern "C" void kernel_launch(void* const* d_in, const int* in_sizes, int n_in,
                              void* d_out, int out_size) {
    const float* x     = (const float*)d_in[0];  // (512,1024,1,68)
    const float* w1    = (const float*)d_in[1];  // (256,1024)
    const float* b1    = (const float*)d_in[2];  // (256,)
    const float* w2    = (const float*)d_in[3];  // (2,)
    const float* b2    = (const float*)d_in[4];  // scalar
    const float* gamma = (const float*)d_in[5];  // (1024,)
    const float* beta  = (const float*)d_in[6];  // (1024,)
    float* out = (float*)d_out;

    kAT<<<4096 + 2048, 128>>>(x, w1);
    kB<<<128, 256>>>(b1);
    kC<<<dim3(4, 32), 256>>>(w2, b2, gamma, beta);
    kD<<<4096, 128>>>(x, out);
}

// round 13
// speedup vs baseline: 2.8842x; 1.1179x over previous
#include <cuda_runtime.h>
#include <cstdint>

#define NB   512
#define CB   1024
#define VB   68
#define PB   7
#define OB   256   // C/4
#define NP   4096  // NB * 8 (p padded to 8)
#define WPAD 264   // 256 + 8  -> bank-bijective fragment loads
#define XPAD 40    // 32 + 8

// ---------------- scratch (device globals; no allocation allowed) ----------
__device__ float  g_S2[NB * CB * 8];    // part-wise sums of x^2
__device__ float  g_X [CB * NP];        // mean-pooled x_parts (tf32), [c][np]
__device__ float  g_Wt[CB * OB];        // transposed conv1 weight (tf32): [c][o]
__device__ float2 g_pool[NP];           // per np: (sum, max) over all 256 o
__device__ float  g_att[NB * 8];        // softmax attention per (n, p), padded
__device__ float  g_part[32 * CB * 2];  // partial BN sums (32 n-chunks)
__device__ float2 g_ss[CB];             // (scale, shift) per channel
__device__ int    g_cnt[4];             // last-block counters (graph-safe)

__device__ __forceinline__ float tf32r(float x) {
    unsigned u;
    asm("cvt.rna.tf32.f32 %0, %1;" : "=r"(u) : "f"(x));
    return __uint_as_float(u);
}

// ---------------- compile-time joint -> part mapping -----------------------
__device__ __host__ __forceinline__ constexpr int part_of(int v) {
    return v < 17 ? 0 : v < 22 ? 1 : v < 27 ? 2 : v < 36 ? 3 :
           v < 42 ? 4 : v < 48 ? 5 : 6;
}
// runtime arithmetic version (no table, no local memory)
__device__ __forceinline__ int part_rt(int v) {
    return (v >= 17) + (v >= 22) + (v >= 27) + (v >= 36) + (v >= 42) + (v >= 48);
}

template <int VV>
__device__ __forceinline__ void acc_one(float val, float* s1, float* s2) {
    constexpr int j = part_of(VV);
    s1[j] += val;
    s2[j] = fmaf(val, val, s2[j]);
}

template <int I>
__device__ __forceinline__ void acc_loop_s(const float4* xr, float* s1, float* s2) {
    if constexpr (I < 17) {
        float4 q = xr[I];
        acc_one<4 * I + 0>(q.x, s1, s2);
        acc_one<4 * I + 1>(q.y, s1, s2);
        acc_one<4 * I + 2>(q.z, s1, s2);
        acc_one<4 * I + 3>(q.w, s1, s2);
        acc_loop_s<I + 1>(xr, s1, s2);
    }
}

// ---------------- kAT: part sums (cp.async-staged) + W transpose (tf32) -----
// blocks [0, 4096): part sums over 128 rows each; blocks [4096, 6144): kT.
__global__ void __launch_bounds__(128) kAT(const float* __restrict__ x,
                                           const float* __restrict__ w1) {
    int t = threadIdx.x;
    if (blockIdx.x >= 4096) {              // ---- transpose conv1_w, tf32 ----
        int idx = (blockIdx.x - 4096) * 128 + t;   // 0 .. 262143
        int o = idx >> 10;
        int c = idx & 1023;
        g_Wt[c * OB + o] = tf32r(w1[idx]);
        return;
    }
    __shared__ float4 sm[128 * 17];        // 34.8 KB
    const float4* gx = (const float4*)x + (size_t)blockIdx.x * (128 * 17);
    unsigned sb = (unsigned)__cvta_generic_to_shared(sm);
#pragma unroll
    for (int i = 0; i < 17; i++) {
        unsigned dst = sb + (unsigned)(t + i * 128) * 16;
        asm volatile("cp.async.cg.shared.global [%0], [%1], 16;"
                     :: "r"(dst), "l"(gx + t + i * 128));
    }
    asm volatile("cp.async.commit_group;");
    asm volatile("cp.async.wait_group 0;");
    __syncthreads();

    int row = blockIdx.x * 128 + t;
    int n = row >> 10;
    int c = row & 1023;
    float s1[8] = {0, 0, 0, 0, 0, 0, 0, 0};
    float s2[8] = {0, 0, 0, 0, 0, 0, 0, 0};
    acc_loop_s<0>(sm + t * 17, s1, s2);

    float4* o2 = (float4*)(g_S2 + (size_t)row * 8);
    o2[0] = make_float4(s2[0], s2[1], s2[2], s2[3]);
    o2[1] = make_float4(s2[4], s2[5], s2[6], 0.f);
    // transposed mean-pooled layout (tf32). Mean 1/count[p] applied HERE only.
    float4* gxo = (float4*)(g_X + (size_t)c * NP + n * 8);
    gxo[0] = make_float4(tf32r(s1[0] * (1.f / 17.f)), tf32r(s1[1] * (1.f / 5.f)),
                         tf32r(s1[2] * (1.f / 5.f)),  tf32r(s1[3] * (1.f / 9.f)));
    gxo[1] = make_float4(tf32r(s1[4] * (1.f / 6.f)),  tf32r(s1[5] * (1.f / 6.f)),
                         tf32r(s1[6] * (1.f / 20.f)), 0.f);
}

// ---------------- kB: tf32 tensor-core GEMM + pooled epilogue ---------------
// grid 128: bx = np-tile (32 np). 256 threads = 8 warps; full o=256 per block.
__global__ void __launch_bounds__(256) kB(const float* __restrict__ b1) {
    __shared__ float Ws[2][16][WPAD];     // ~33.8 KB
    __shared__ float Xs[2][16][XPAD];     //  ~5.1 KB
    __shared__ float2 red[8][32];
    int t = threadIdx.x;
    int bx = blockIdx.x;
    int w = t >> 5, lane = t & 31;
    int lq = lane >> 2, lr = lane & 3;

    unsigned wb0 = (unsigned)__cvta_generic_to_shared(&Ws[0][0][0]);
    unsigned xb0 = (unsigned)__cvta_generic_to_shared(&Xs[0][0][0]);

    auto load_chunk = [&](int k, int buf) {
        const float* srcW = g_Wt + (size_t)(k * 16) * OB;
        unsigned wb = wb0 + buf * (16 * WPAD * 4);
#pragma unroll
        for (int i = 0; i < 4; i++) {
            int idx = t + i * 256;             // 0..1023
            int cr = idx >> 6, o4 = idx & 63;
            unsigned dst = wb + (cr * WPAD + o4 * 4) * 4;
            asm volatile("cp.async.cg.shared.global [%0], [%1], 16;"
                         :: "r"(dst), "l"(srcW + cr * OB + o4 * 4));
        }
        if (t < 128) {
            int cr = t >> 3, n4 = t & 7;
            unsigned dst = xb0 + buf * (16 * XPAD * 4) + (cr * XPAD + n4 * 4) * 4;
            asm volatile("cp.async.cg.shared.global [%0], [%1], 16;"
                :: "r"(dst), "l"(g_X + (size_t)(k * 16 + cr) * NP + bx * 32 + n4 * 4));
        }
        asm volatile("cp.async.commit_group;");
    };

    float acc[2][4][4];
#pragma unroll
    for (int a = 0; a < 2; a++)
#pragma unroll
        for (int b = 0; b < 4; b++)
#pragma unroll
            for (int r = 0; r < 4; r++) acc[a][b][r] = 0.f;

    load_chunk(0, 0);
    for (int k = 0; k < 64; k++) {
        int buf = k & 1;
        if (k < 63) {
            load_chunk(k + 1, buf ^ 1);
            asm volatile("cp.async.wait_group 1;");
        } else {
            asm volatile("cp.async.wait_group 0;");
        }
        __syncthreads();

#pragma unroll
        for (int s = 0; s < 2; s++) {
            int kl = s * 8;
            unsigned bf[4][2];
#pragma unroll
            for (int nt = 0; nt < 4; nt++) {
                bf[nt][0] = __float_as_uint(Xs[buf][kl + lr][nt * 8 + lq]);
                bf[nt][1] = __float_as_uint(Xs[buf][kl + lr + 4][nt * 8 + lq]);
            }
#pragma unroll
            for (int mi = 0; mi < 2; mi++) {
                int ob = (w * 2 + mi) * 16 + lq;
                unsigned a0 = __float_as_uint(Ws[buf][kl + lr][ob]);
                unsigned a1 = __float_as_uint(Ws[buf][kl + lr][ob + 8]);
                unsigned a2 = __float_as_uint(Ws[buf][kl + lr + 4][ob]);
                unsigned a3 = __float_as_uint(Ws[buf][kl + lr + 4][ob + 8]);
#pragma unroll
                for (int nt = 0; nt < 4; nt++) {
                    asm("mma.sync.aligned.m16n8k8.row.col.f32.tf32.tf32.f32 "
                        "{%0,%1,%2,%3}, {%4,%5,%6,%7}, {%8,%9}, {%0,%1,%2,%3};"
                        : "+f"(acc[mi][nt][0]), "+f"(acc[mi][nt][1]),
                          "+f"(acc[mi][nt][2]), "+f"(acc[mi][nt][3])
                        : "r"(a0), "r"(a1), "r"(a2), "r"(a3),
                          "r"(bf[nt][0]), "r"(bf[nt][1]));
                }
            }
        }
        __syncthreads();
    }

    // ---- epilogue: bias, per-np sum & max over all o (g_X already means) ----
    float br0 = __ldg(b1 + w * 32 + lq);
    float br1 = __ldg(b1 + w * 32 + lq + 8);
    float br2 = __ldg(b1 + w * 32 + 16 + lq);
    float br3 = __ldg(b1 + w * 32 + 16 + lq + 8);

#pragma unroll
    for (int nt = 0; nt < 4; nt++) {
        float he0 = acc[0][nt][0] + br0;
        float ho0 = acc[0][nt][1] + br0;
        float he1 = acc[0][nt][2] + br1;
        float ho1 = acc[0][nt][3] + br1;
        float he2 = acc[1][nt][0] + br2;
        float ho2 = acc[1][nt][1] + br2;
        float he3 = acc[1][nt][2] + br3;
        float ho3 = acc[1][nt][3] + br3;
        float se = he0 + he1 + he2 + he3;
        float so = ho0 + ho1 + ho2 + ho3;
        float me = fmaxf(fmaxf(he0, he1), fmaxf(he2, he3));
        float mo = fmaxf(fmaxf(ho0, ho1), fmaxf(ho2, ho3));
#pragma unroll
        for (int off = 4; off < 32; off <<= 1) {
            se += __shfl_xor_sync(0xffffffffu, se, off);
            so += __shfl_xor_sync(0xffffffffu, so, off);
            me = fmaxf(me, __shfl_xor_sync(0xffffffffu, me, off));
            mo = fmaxf(mo, __shfl_xor_sync(0xffffffffu, mo, off));
        }
        if (lq == 0) {
            red[w][nt * 8 + 2 * lr]     = make_float2(se, me);
            red[w][nt * 8 + 2 * lr + 1] = make_float2(so, mo);
        }
    }
    __syncthreads();
    if (t < 32) {
        float s = 0.f, m = -3.402823e38f;
#pragma unroll
        for (int ww = 0; ww < 8; ww++) {
            float2 v = red[ww][t];
            s += v.x;
            m = fmaxf(m, v.y);
        }
        g_pool[bx * 32 + t] = make_float2(s, m);
    }
}

// ---------------- kC: softmax + BN sums + fused last-block scale/shift ------
// grid (4, 32): x -> channel chunk (256 ch), y -> n chunk (16).
__global__ void __launch_bounds__(256) kC(const float* __restrict__ w2,
                                          const float* __restrict__ b2c,
                                          const float* __restrict__ gamma,
                                          const float* __restrict__ beta) {
    __shared__ float sa[16][8];    // att * count[p]  (mean sums over g_X)
    __shared__ float sa2[16][8];   // att^2           (raw g_S2 sums)
    __shared__ int is_last;
    int c = blockIdx.x * 256 + threadIdx.x;
    int n0 = blockIdx.y * 16;

    if (threadIdx.x < 16) {
        int n = n0 + threadIdx.x;
        float w2a = __ldg(w2), w2b = __ldg(w2 + 1), bb = __ldg(b2c);
        float lg[PB];
        float mxv = -3.402823e38f;
#pragma unroll
        for (int p = 0; p < PB; p++) {
            float2 a0 = g_pool[n * 8 + p];
            lg[p] = fmaf(w2a, a0.x * (1.f / 256.f), fmaf(w2b, a0.y, bb));
            mxv = fmaxf(mxv, lg[p]);
        }
        float e[PB], ss = 0.f;
#pragma unroll
        for (int p = 0; p < PB; p++) { e[p] = expf(lg[p] - mxv); ss += e[p]; }
        float inv = 1.f / ss;
        const float cnt[7] = {17.f, 5.f, 5.f, 9.f, 6.f, 6.f, 20.f};
#pragma unroll
        for (int p = 0; p < PB; p++) {
            float a = e[p] * inv;
            sa[threadIdx.x][p] = a * cnt[p];
            sa2[threadIdx.x][p] = a * a;
            if (blockIdx.x == 0) g_att[n * 8 + p] = a;
        }
        sa[threadIdx.x][7] = 0.f;
        sa2[threadIdx.x][7] = 0.f;
        if (blockIdx.x == 0) g_att[n * 8 + 7] = 0.f;
    }
    __syncthreads();

    float sY = 0.f, sY2 = 0.f;
    const float4* px = (const float4*)(g_X + (size_t)c * NP + n0 * 8);
#pragma unroll 4
    for (int nn = 0; nn < 16; nn++) {
        float4 q0 = __ldg(px + nn * 2), q1 = __ldg(px + nn * 2 + 1);
        size_t b2s = ((size_t)(n0 + nn) * CB + c) * 8;
        const float4* p2 = (const float4*)(g_S2 + b2s);
        float4 r0 = __ldg(p2), r1 = __ldg(p2 + 1);
        const float* a  = sa[nn];
        const float* a2 = sa2[nn];
        sY  = fmaf(q0.x, a[0], fmaf(q0.y, a[1], fmaf(q0.z, a[2], fmaf(q0.w, a[3],
              fmaf(q1.x, a[4], fmaf(q1.y, a[5], fmaf(q1.z, a[6], sY)))))));
        sY2 = fmaf(r0.x, a2[0], fmaf(r0.y, a2[1], fmaf(r0.z, a2[2], fmaf(r0.w, a2[3],
              fmaf(r1.x, a2[4], fmaf(r1.y, a2[5], fmaf(r1.z, a2[6], sY2)))))));
    }
    size_t oidx = ((size_t)blockIdx.y * CB + c) * 2;
    g_part[oidx]     = sY;
    g_part[oidx + 1] = sY2;

    // ---- last-block reduction for this channel chunk ----
    __threadfence();
    if (threadIdx.x == 0)
        is_last = (atomicAdd(&g_cnt[blockIdx.x], 1) == 31);
    __syncthreads();
    if (is_last) {
        float tY = 0.f, tY2 = 0.f;
#pragma unroll
        for (int w = 0; w < 32; w++) {
            float2 v = __ldcg((const float2*)(g_part + ((size_t)w * CB + c) * 2));
            tY += v.x;
            tY2 += v.y;
        }
        const float inv = 1.f / (512.f * 68.f);
        float mean = tY * inv;
        float var = fmaf(-mean, mean, tY2 * inv);
        float sc = __ldg(gamma + c) * rsqrtf(var + 1e-5f);
        g_ss[c] = make_float2(sc, fmaf(-mean, sc, __ldg(beta + c)));
        if (threadIdx.x == 0) atomicExch(&g_cnt[blockIdx.x], 0);  // graph-safe
    }
}

// ---------------- kD: streaming scale+BN+residual+ReLU (no smem) ------------
// 4096 blocks x 128 threads, reverse order. Each block = 128 rows = one n.
// Per float4 g: row r=g/17 (c = c0+r), slot s=g%17, joints 4s..4s+3.
// part computed arithmetically; att[p] fetched via width-8 shfl.
__global__ void __launch_bounds__(128) kD(const float* __restrict__ x,
                                          float* __restrict__ out) {
    int t = threadIdx.x;
    int bid = 4095 - blockIdx.x;           // reverse: reuse x tail from L2
    int n = bid >> 3;                      // 8 blocks per n
    int c0 = (bid & 7) * 128;
    float att_reg = __ldg(g_att + n * 8 + (t & 7));

    size_t base = (size_t)bid * 2176;      // float4 units (128*17)
    const float4* gx = (const float4*)x + base;
    float4* go = (float4*)out + base;

#pragma unroll
    for (int i = 0; i < 17; i++) {
        int g = i * 128 + t;               // 0..2175
        int r = g / 17;
        int s = g - r * 17;
        float4 q = __ldg(gx + g);
        float2 ss = __ldg(&g_ss[c0 + r]);
        int v0 = 4 * s;
        int p0 = part_rt(v0);
        int p1 = part_rt(v0 + 1);
        int p2 = part_rt(v0 + 2);
        int p3 = part_rt(v0 + 3);
        float a0 = __shfl_sync(0xffffffffu, att_reg, p0, 8);
        float a1 = __shfl_sync(0xffffffffu, att_reg, p1, 8);
        float a2 = __shfl_sync(0xffffffffu, att_reg, p2, 8);
        float a3 = __shfl_sync(0xffffffffu, att_reg, p3, 8);
        q.x = fmaxf(fmaf(q.x, fmaf(a0, ss.x, 1.f), ss.y), 0.f);
        q.y = fmaxf(fmaf(q.y, fmaf(a1, ss.x, 1.f), ss.y), 0.f);
        q.z = fmaxf(fmaf(q.z, fmaf(a2, ss.x, 1.f), ss.y), 0.f);
        q.w = fmaxf(fmaf(q.w, fmaf(a3, ss.x, 1.f), ss.y), 0.f);
        go[g] = q;
    }
}

// ---------------- launch ----------------------------------------------------
extern "C" void kernel_launch(void* const* d_in, const int* in_sizes, int n_in,
                              void* d_out, int out_size) {
    const float* x     = (const float*)d_in[0];  // (512,1024,1,68)
    const float* w1    = (const float*)d_in[1];  // (256,1024)
    const float* b1    = (const float*)d_in[2];  // (256,)
    const float* w2    = (const float*)d_in[3];  // (2,)
    const float* b2    = (const float*)d_in[4];  // scalar
    const float* gamma = (const float*)d_in[5];  // (1024,)
    const float* beta  = (const float*)d_in[6];  // (1024,)
    float* out = (float*)d_out;

    kAT<<<4096 + 2048, 128>>>(x, w1);
    kB<<<128, 256>>>(b1);
    kC<<<dim3(4, 32), 256>>>(w2, b2, gamma, beta);
    kD<<<4096, 128>>>(x, out);
}

// round 15
// speedup vs baseline: 3.0369x; 1.0529x over previous
#include <cuda_runtime.h>
#include <cuda_fp16.h>
#include <cstdint>

#define NB   512
#define CB   1024
#define VB   68
#define PB   7
#define OB   256   // C/4
#define NP   4096  // NB * 8 (p padded to 8)
#define WPAD 264   // 256 + 8  -> bank-bijective fragment loads
#define XPAD 40    // 32 + 8

// ---------------- scratch (device globals; no allocation allowed) ----------
__device__ __half2 g_S2h[NB * CB * 4];  // part-wise sums of x^2 (fp16, packed)
__device__ float  g_X [CB * NP];        // mean-pooled x_parts (tf32), [c][np]
__device__ float  g_Wt[CB * OB];        // transposed conv1 weight (tf32): [c][o]
__device__ float2 g_pool[NP];           // per np: (sum, max) over all 256 o
__device__ float  g_attj[NB * VB];      // attention expanded to joints, [n][v]
__device__ float  g_part[32 * CB * 2];  // partial BN sums (32 n-chunks)
__device__ float2 g_ss[CB];             // (scale, shift) per channel
__device__ int    g_cnt[4];             // last-block counters (graph-safe)

__device__ __forceinline__ float tf32r(float x) {
    unsigned u;
    asm("cvt.rna.tf32.f32 %0, %1;" : "=r"(u) : "f"(x));
    return __uint_as_float(u);
}

// ---------------- compile-time joint -> part mapping -----------------------
__device__ __host__ __forceinline__ constexpr int part_of(int v) {
    return v < 17 ? 0 : v < 22 ? 1 : v < 27 ? 2 : v < 36 ? 3 :
           v < 42 ? 4 : v < 48 ? 5 : 6;
}

template <int VV>
__device__ __forceinline__ void acc_one(float val, float* s1, float* s2) {
    constexpr int j = part_of(VV);
    s1[j] += val;
    s2[j] = fmaf(val, val, s2[j]);
}

template <int I>
__device__ __forceinline__ void acc_loop_s(const float4* xr, float* s1, float* s2) {
    if constexpr (I < 17) {
        float4 q = xr[I];
        acc_one<4 * I + 0>(q.x, s1, s2);
        acc_one<4 * I + 1>(q.y, s1, s2);
        acc_one<4 * I + 2>(q.z, s1, s2);
        acc_one<4 * I + 3>(q.w, s1, s2);
        acc_loop_s<I + 1>(xr, s1, s2);
    }
}

template <int I>
__device__ __forceinline__ void attj_store(float* dst, const float* av) {
    if constexpr (I < VB) {
        dst[I] = av[part_of(I)];       // constexpr index -> register
        attj_store<I + 1>(dst, av);
    }
}

// ---------------- kAT: part sums (cp.async-staged) + W transpose (tf32) -----
// blocks [0, 4096): part sums over 128 rows each; blocks [4096, 6144): kT.
__global__ void __launch_bounds__(128) kAT(const float* __restrict__ x,
                                           const float* __restrict__ w1) {
    int t = threadIdx.x;
    if (blockIdx.x >= 4096) {              // ---- transpose conv1_w, tf32 ----
        int idx = (blockIdx.x - 4096) * 128 + t;   // 0 .. 262143
        int o = idx >> 10;
        int c = idx & 1023;
        g_Wt[c * OB + o] = tf32r(w1[idx]);
        return;
    }
    __shared__ float4 sm[128 * 17];        // 34.8 KB
    const float4* gx = (const float4*)x + (size_t)blockIdx.x * (128 * 17);
    unsigned sb = (unsigned)__cvta_generic_to_shared(sm);
#pragma unroll
    for (int i = 0; i < 17; i++) {
        unsigned dst = sb + (unsigned)(t + i * 128) * 16;
        asm volatile("cp.async.cg.shared.global [%0], [%1], 16;"
                     :: "r"(dst), "l"(gx + t + i * 128));
    }
    asm volatile("cp.async.commit_group;");
    asm volatile("cp.async.wait_group 0;");
    __syncthreads();

    int row = blockIdx.x * 128 + t;
    int n = row >> 10;
    int c = row & 1023;
    float s1[8] = {0, 0, 0, 0, 0, 0, 0, 0};
    float s2[8] = {0, 0, 0, 0, 0, 0, 0, 0};
    acc_loop_s<0>(sm + t * 17, s1, s2);

    // S2 packed as 8 halves (16 B) per row
    __half2 h0 = __floats2half2_rn(s2[0], s2[1]);
    __half2 h1 = __floats2half2_rn(s2[2], s2[3]);
    __half2 h2 = __floats2half2_rn(s2[4], s2[5]);
    __half2 h3 = __floats2half2_rn(s2[6], 0.f);
    uint4 pk;
    pk.x = *(unsigned*)&h0; pk.y = *(unsigned*)&h1;
    pk.z = *(unsigned*)&h2; pk.w = *(unsigned*)&h3;
    *(uint4*)(g_S2h + (size_t)row * 4) = pk;

    // transposed mean-pooled layout (tf32). Mean 1/count[p] applied HERE only.
    float4* gxo = (float4*)(g_X + (size_t)c * NP + n * 8);
    gxo[0] = make_float4(tf32r(s1[0] * (1.f / 17.f)), tf32r(s1[1] * (1.f / 5.f)),
                         tf32r(s1[2] * (1.f / 5.f)),  tf32r(s1[3] * (1.f / 9.f)));
    gxo[1] = make_float4(tf32r(s1[4] * (1.f / 6.f)),  tf32r(s1[5] * (1.f / 6.f)),
                         tf32r(s1[6] * (1.f / 20.f)), 0.f);
}

// ---------------- kB: tf32 tensor-core GEMM + pooled epilogue ---------------
// grid 128: bx = np-tile (32 np). 256 threads = 8 warps; full o=256 per block.
__global__ void __launch_bounds__(256) kB(const float* __restrict__ b1) {
    __shared__ float Ws[2][16][WPAD];     // ~33.8 KB
    __shared__ float Xs[2][16][XPAD];     //  ~5.1 KB
    __shared__ float2 red[8][32];
    int t = threadIdx.x;
    int bx = blockIdx.x;
    int w = t >> 5, lane = t & 31;
    int lq = lane >> 2, lr = lane & 3;

    unsigned wb0 = (unsigned)__cvta_generic_to_shared(&Ws[0][0][0]);
    unsigned xb0 = (unsigned)__cvta_generic_to_shared(&Xs[0][0][0]);

    auto load_chunk = [&](int k, int buf) {
        const float* srcW = g_Wt + (size_t)(k * 16) * OB;
        unsigned wb = wb0 + buf * (16 * WPAD * 4);
#pragma unroll
        for (int i = 0; i < 4; i++) {
            int idx = t + i * 256;             // 0..1023
            int cr = idx >> 6, o4 = idx & 63;
            unsigned dst = wb + (cr * WPAD + o4 * 4) * 4;
            asm volatile("cp.async.cg.shared.global [%0], [%1], 16;"
                         :: "r"(dst), "l"(srcW + cr * OB + o4 * 4));
        }
        if (t < 128) {
            int cr = t >> 3, n4 = t & 7;
            unsigned dst = xb0 + buf * (16 * XPAD * 4) + (cr * XPAD + n4 * 4) * 4;
            asm volatile("cp.async.cg.shared.global [%0], [%1], 16;"
                :: "r"(dst), "l"(g_X + (size_t)(k * 16 + cr) * NP + bx * 32 + n4 * 4));
        }
        asm volatile("cp.async.commit_group;");
    };

    float acc[2][4][4];
#pragma unroll
    for (int a = 0; a < 2; a++)
#pragma unroll
        for (int b = 0; b < 4; b++)
#pragma unroll
            for (int r = 0; r < 4; r++) acc[a][b][r] = 0.f;

    load_chunk(0, 0);
    for (int k = 0; k < 64; k++) {
        int buf = k & 1;
        if (k < 63) {
            load_chunk(k + 1, buf ^ 1);
            asm volatile("cp.async.wait_group 1;");
        } else {
            asm volatile("cp.async.wait_group 0;");
        }
        __syncthreads();

#pragma unroll
        for (int s = 0; s < 2; s++) {
            int kl = s * 8;
            unsigned bf[4][2];
#pragma unroll
            for (int nt = 0; nt < 4; nt++) {
                bf[nt][0] = __float_as_uint(Xs[buf][kl + lr][nt * 8 + lq]);
                bf[nt][1] = __float_as_uint(Xs[buf][kl + lr + 4][nt * 8 + lq]);
            }
#pragma unroll
            for (int mi = 0; mi < 2; mi++) {
                int ob = (w * 2 + mi) * 16 + lq;
                unsigned a0 = __float_as_uint(Ws[buf][kl + lr][ob]);
                unsigned a1 = __float_as_uint(Ws[buf][kl + lr][ob + 8]);
                unsigned a2 = __float_as_uint(Ws[buf][kl + lr + 4][ob]);
                unsigned a3 = __float_as_uint(Ws[buf][kl + lr + 4][ob + 8]);
#pragma unroll
                for (int nt = 0; nt < 4; nt++) {
                    asm("mma.sync.aligned.m16n8k8.row.col.f32.tf32.tf32.f32 "
                        "{%0,%1,%2,%3}, {%4,%5,%6,%7}, {%8,%9}, {%0,%1,%2,%3};"
                        : "+f"(acc[mi][nt][0]), "+f"(acc[mi][nt][1]),
                          "+f"(acc[mi][nt][2]), "+f"(acc[mi][nt][3])
                        : "r"(a0), "r"(a1), "r"(a2), "r"(a3),
                          "r"(bf[nt][0]), "r"(bf[nt][1]));
                }
            }
        }
        __syncthreads();
    }

    // ---- epilogue: bias, per-np sum & max over all o (g_X already means) ----
    float br0 = __ldg(b1 + w * 32 + lq);
    float br1 = __ldg(b1 + w * 32 + lq + 8);
    float br2 = __ldg(b1 + w * 32 + 16 + lq);
    float br3 = __ldg(b1 + w * 32 + 16 + lq + 8);

#pragma unroll
    for (int nt = 0; nt < 4; nt++) {
        float he0 = acc[0][nt][0] + br0;
        float ho0 = acc[0][nt][1] + br0;
        float he1 = acc[0][nt][2] + br1;
        float ho1 = acc[0][nt][3] + br1;
        float he2 = acc[1][nt][0] + br2;
        float ho2 = acc[1][nt][1] + br2;
        float he3 = acc[1][nt][2] + br3;
        float ho3 = acc[1][nt][3] + br3;
        float se = he0 + he1 + he2 + he3;
        float so = ho0 + ho1 + ho2 + ho3;
        float me = fmaxf(fmaxf(he0, he1), fmaxf(he2, he3));
        float mo = fmaxf(fmaxf(ho0, ho1), fmaxf(ho2, ho3));
#pragma unroll
        for (int off = 4; off < 32; off <<= 1) {
            se += __shfl_xor_sync(0xffffffffu, se, off);
            so += __shfl_xor_sync(0xffffffffu, so, off);
            me = fmaxf(me, __shfl_xor_sync(0xffffffffu, me, off));
            mo = fmaxf(mo, __shfl_xor_sync(0xffffffffu, mo, off));
        }
        if (lq == 0) {
            red[w][nt * 8 + 2 * lr]     = make_float2(se, me);
            red[w][nt * 8 + 2 * lr + 1] = make_float2(so, mo);
        }
    }
    __syncthreads();
    if (t < 32) {
        float s = 0.f, m = -3.402823e38f;
#pragma unroll
        for (int ww = 0; ww < 8; ww++) {
            float2 v = red[ww][t];
            s += v.x;
            m = fmaxf(m, v.y);
        }
        g_pool[bx * 32 + t] = make_float2(s, m);
    }
}

// ---------------- kC: softmax + BN sums + fused last-block scale/shift ------
// grid (4, 32): x -> channel chunk (256 ch), y -> n chunk (16).
__global__ void __launch_bounds__(256) kC(const float* __restrict__ w2,
                                          const float* __restrict__ b2c,
                                          const float* __restrict__ gamma,
                                          const float* __restrict__ beta) {
    __shared__ float sa[16][8];    // att * count[p]  (mean sums over g_X)
    __shared__ float sa2[16][8];   // att^2           (raw S2 sums)
    __shared__ int is_last;
    int c = blockIdx.x * 256 + threadIdx.x;
    int n0 = blockIdx.y * 16;

    if (threadIdx.x < 16) {
        int n = n0 + threadIdx.x;
        float w2a = __ldg(w2), w2b = __ldg(w2 + 1), bb = __ldg(b2c);
        float lg[PB];
        float mxv = -3.402823e38f;
#pragma unroll
        for (int p = 0; p < PB; p++) {
            float2 a0 = g_pool[n * 8 + p];
            lg[p] = fmaf(w2a, a0.x * (1.f / 256.f), fmaf(w2b, a0.y, bb));
            mxv = fmaxf(mxv, lg[p]);
        }
        float e[PB], ss = 0.f;
#pragma unroll
        for (int p = 0; p < PB; p++) { e[p] = expf(lg[p] - mxv); ss += e[p]; }
        float inv = 1.f / ss;
        const float cnt[7] = {17.f, 5.f, 5.f, 9.f, 6.f, 6.f, 20.f};
        float av[PB];
#pragma unroll
        for (int p = 0; p < PB; p++) {
            av[p] = e[p] * inv;
            sa[threadIdx.x][p] = av[p] * cnt[p];
            sa2[threadIdx.x][p] = av[p] * av[p];
        }
        sa[threadIdx.x][7] = 0.f;
        sa2[threadIdx.x][7] = 0.f;
        if (blockIdx.x == 0) attj_store<0>(g_attj + n * VB, av);
    }
    __syncthreads();

    float sY = 0.f, sY2 = 0.f;
    const float4* px = (const float4*)(g_X + (size_t)c * NP + n0 * 8);
#pragma unroll 4
    for (int nn = 0; nn < 16; nn++) {
        float4 q0 = __ldg(px + nn * 2), q1 = __ldg(px + nn * 2 + 1);
        uint4 u = __ldg((const uint4*)(g_S2h + ((size_t)(n0 + nn) * CB + c) * 4));
        float2 r0 = __half22float2(*(__half2*)&u.x);
        float2 r1 = __half22float2(*(__half2*)&u.y);
        float2 r2 = __half22float2(*(__half2*)&u.z);
        float2 r3 = __half22float2(*(__half2*)&u.w);
        const float* a  = sa[nn];
        const float* a2 = sa2[nn];
        sY  = fmaf(q0.x, a[0], fmaf(q0.y, a[1], fmaf(q0.z, a[2], fmaf(q0.w, a[3],
              fmaf(q1.x, a[4], fmaf(q1.y, a[5], fmaf(q1.z, a[6], sY)))))));
        sY2 = fmaf(r0.x, a2[0], fmaf(r0.y, a2[1], fmaf(r1.x, a2[2], fmaf(r1.y, a2[3],
              fmaf(r2.x, a2[4], fmaf(r2.y, a2[5], fmaf(r3.x, a2[6], sY2)))))));
    }
    size_t oidx = ((size_t)blockIdx.y * CB + c) * 2;
    g_part[oidx]     = sY;
    g_part[oidx + 1] = sY2;

    // ---- last-block reduction for this channel chunk ----
    __threadfence();
    if (threadIdx.x == 0)
        is_last = (atomicAdd(&g_cnt[blockIdx.x], 1) == 31);
    __syncthreads();
    if (is_last) {
        float tY = 0.f, tY2 = 0.f;
#pragma unroll
        for (int w = 0; w < 32; w++) {
            float2 v = __ldcg((const float2*)(g_part + ((size_t)w * CB + c) * 2));
            tY += v.x;
            tY2 += v.y;
        }
        const float inv = 1.f / (512.f * 68.f);
        float mean = tY * inv;
        float var = fmaf(-mean, mean, tY2 * inv);
        float sc = __ldg(gamma + c) * rsqrtf(var + 1e-5f);
        g_ss[c] = make_float2(sc, fmaf(-mean, sc, __ldg(beta + c)));
        if (threadIdx.x == 0) atomicExch(&g_cnt[blockIdx.x], 0);  // graph-safe
    }
}

// ---------------- kD: streaming scale+BN+residual+ReLU (no smem) ------------
// 4096 blocks x 128 threads, reverse order. Each block = 128 rows = one n.
// Per float4 g: row r=g/17 (c=c0+r), slot s=g%17; attention comes from the
// joint-expanded table g_attj (L1-resident, 272 B per n).
__global__ void __launch_bounds__(128) kD(const float* __restrict__ x,
                                          float* __restrict__ out) {
    int t = threadIdx.x;
    int bid = 4095 - blockIdx.x;           // reverse: reuse x tail from L2
    int n = bid >> 3;                      // 8 blocks per n
    int c0 = (bid & 7) * 128;

    size_t base = (size_t)bid * 2176;      // float4 units (128*17)
    const float4* gx = (const float4*)x + base;
    float4* go = (float4*)out + base;
    const float4* aj = (const float4*)(g_attj + n * VB);

#pragma unroll
    for (int i = 0; i < 17; i++) {
        int g = i * 128 + t;               // 0..2175
        int r = g / 17;                    // magic-mul
        int s = g - r * 17;
        float4 q = __ldg(gx + g);
        float4 a = __ldg(aj + s);
        float2 ss = __ldg(&g_ss[c0 + r]);
        q.x = fmaxf(fmaf(q.x, fmaf(a.x, ss.x, 1.f), ss.y), 0.f);
        q.y = fmaxf(fmaf(q.y, fmaf(a.y, ss.x, 1.f), ss.y), 0.f);
        q.z = fmaxf(fmaf(q.z, fmaf(a.z, ss.x, 1.f), ss.y), 0.f);
        q.w = fmaxf(fmaf(q.w, fmaf(a.w, ss.x, 1.f), ss.y), 0.f);
        go[g] = q;
    }
}

// ---------------- launch ----------------------------------------------------
extern "C" void kernel_launch(void* const* d_in, const int* in_sizes, int n_in,
                              void* d_out, int out_size) {
    const float* x     = (const float*)d_in[0];  // (512,1024,1,68)
    const float* w1    = (const float*)d_in[1];  // (256,1024)
    const float* b1    = (const float*)d_in[2];  // (256,)
    const float* w2    = (const float*)d_in[3];  // (2,)
    const float* b2    = (const float*)d_in[4];  // scalar
    const float* gamma = (const float*)d_in[5];  // (1024,)
    const float* beta  = (const float*)d_in[6];  // (1024,)
    float* out = (float*)d_out;

    kAT<<<4096 + 2048, 128>>>(x, w1);
    kB<<<128, 256>>>(b1);
    kC<<<dim3(4, 32), 256>>>(w2, b2, gamma, beta);
    kD<<<4096, 128>>>(x, out);
}

// round 17
// speedup vs baseline: 3.0961x; 1.0195x over previous
#include <cuda_runtime.h>
#include <cuda_fp16.h>
#include <cstdint>

#define NB   512
#define CB   1024
#define VB   68
#define PB   7
#define OB   256   // C/4
#define NP   4096  // NB * 8 (p padded to 8)
#define WPAD 264   // 256 + 8  -> bank-bijective fragment loads
#define XPAD 40    // 32 + 8

// ---------------- scratch (device globals; no allocation allowed) ----------
__device__ __half2 g_S2h[NB * CB * 4];  // part-wise sums of x^2 (fp16, packed)
__device__ float  g_X [CB * NP];        // mean-pooled x_parts (tf32), [c][np]
__device__ float  g_Wt[CB * OB];        // transposed conv1 weight (tf32): [c][o]
__device__ float  g_att[NB * 8];        // softmax attention per (n, p), padded
__device__ float  g_attj[NB * VB];      // attention expanded to joints, [n][v]
__device__ float  g_part[32 * CB * 2];  // partial BN sums (32 n-chunks)
__device__ float2 g_ss[CB];             // (scale, shift) per channel
__device__ int    g_cnt[4];             // last-block counters (graph-safe)

__device__ __forceinline__ float tf32r(float x) {
    unsigned u;
    asm("cvt.rna.tf32.f32 %0, %1;" : "=r"(u) : "f"(x));
    return __uint_as_float(u);
}

// ---------------- compile-time joint -> part mapping -----------------------
__device__ __host__ __forceinline__ constexpr int part_of(int v) {
    return v < 17 ? 0 : v < 22 ? 1 : v < 27 ? 2 : v < 36 ? 3 :
           v < 42 ? 4 : v < 48 ? 5 : 6;
}

template <int VV>
__device__ __forceinline__ void acc_one(float val, float* s1, float* s2) {
    constexpr int j = part_of(VV);
    s1[j] += val;
    s2[j] = fmaf(val, val, s2[j]);
}

template <int I>
__device__ __forceinline__ void acc_loop_s(const float4* xr, float* s1, float* s2) {
    if constexpr (I < 17) {
        float4 q = xr[I];
        acc_one<4 * I + 0>(q.x, s1, s2);
        acc_one<4 * I + 1>(q.y, s1, s2);
        acc_one<4 * I + 2>(q.z, s1, s2);
        acc_one<4 * I + 3>(q.w, s1, s2);
        acc_loop_s<I + 1>(xr, s1, s2);
    }
}

template <int I>
__device__ __forceinline__ void attj_store(float* dst, const float* av) {
    if constexpr (I < VB) {
        dst[I] = av[part_of(I)];       // constexpr index -> register
        attj_store<I + 1>(dst, av);
    }
}

// ---------------- kAT: part sums (cp.async-staged) + W transpose (tf32) -----
// blocks [0, 4096): part sums over 128 rows each; blocks [4096, 6144): kT.
__global__ void __launch_bounds__(128) kAT(const float* __restrict__ x,
                                           const float* __restrict__ w1) {
    int t = threadIdx.x;
    if (blockIdx.x >= 4096) {              // ---- transpose conv1_w, tf32 ----
        int idx = (blockIdx.x - 4096) * 128 + t;   // 0 .. 262143
        int o = idx >> 10;
        int c = idx & 1023;
        g_Wt[c * OB + o] = tf32r(w1[idx]);
        return;
    }
    __shared__ float4 sm[128 * 17];        // 34.8 KB
    const float4* gx = (const float4*)x + (size_t)blockIdx.x * (128 * 17);
    unsigned sb = (unsigned)__cvta_generic_to_shared(sm);
#pragma unroll
    for (int i = 0; i < 17; i++) {
        unsigned dst = sb + (unsigned)(t + i * 128) * 16;
        asm volatile("cp.async.cg.shared.global [%0], [%1], 16;"
                     :: "r"(dst), "l"(gx + t + i * 128));
    }
    asm volatile("cp.async.commit_group;");
    asm volatile("cp.async.wait_group 0;");
    __syncthreads();

    int row = blockIdx.x * 128 + t;
    int n = row >> 10;
    int c = row & 1023;
    float s1[8] = {0, 0, 0, 0, 0, 0, 0, 0};
    float s2[8] = {0, 0, 0, 0, 0, 0, 0, 0};
    acc_loop_s<0>(sm + t * 17, s1, s2);

    // S2 packed as 8 halves (16 B) per row
    __half2 h0 = __floats2half2_rn(s2[0], s2[1]);
    __half2 h1 = __floats2half2_rn(s2[2], s2[3]);
    __half2 h2 = __floats2half2_rn(s2[4], s2[5]);
    __half2 h3 = __floats2half2_rn(s2[6], 0.f);
    uint4 pk;
    pk.x = *(unsigned*)&h0; pk.y = *(unsigned*)&h1;
    pk.z = *(unsigned*)&h2; pk.w = *(unsigned*)&h3;
    *(uint4*)(g_S2h + (size_t)row * 4) = pk;

    // transposed mean-pooled layout (tf32). Mean 1/count[p] applied HERE only.
    float4* gxo = (float4*)(g_X + (size_t)c * NP + n * 8);
    gxo[0] = make_float4(tf32r(s1[0] * (1.f / 17.f)), tf32r(s1[1] * (1.f / 5.f)),
                         tf32r(s1[2] * (1.f / 5.f)),  tf32r(s1[3] * (1.f / 9.f)));
    gxo[1] = make_float4(tf32r(s1[4] * (1.f / 6.f)),  tf32r(s1[5] * (1.f / 6.f)),
                         tf32r(s1[6] * (1.f / 20.f)), 0.f);
}

// ---------------- kB: tf32 tensor-core GEMM + fused softmax epilogue --------
// grid 128: bx = np-tile (32 np = 4 n). 256 threads = 8 warps; o=256 per blk.
__global__ void __launch_bounds__(256) kB(const float* __restrict__ b1,
                                          const float* __restrict__ w2,
                                          const float* __restrict__ b2c) {
    __shared__ float Ws[2][16][WPAD];     // ~33.8 KB
    __shared__ float Xs[2][16][XPAD];     //  ~5.1 KB
    __shared__ float2 red[8][32];
    __shared__ float2 pool_s[32];
    int t = threadIdx.x;
    int bx = blockIdx.x;
    int w = t >> 5, lane = t & 31;
    int lq = lane >> 2, lr = lane & 3;

    unsigned wb0 = (unsigned)__cvta_generic_to_shared(&Ws[0][0][0]);
    unsigned xb0 = (unsigned)__cvta_generic_to_shared(&Xs[0][0][0]);

    auto load_chunk = [&](int k, int buf) {
        const float* srcW = g_Wt + (size_t)(k * 16) * OB;
        unsigned wb = wb0 + buf * (16 * WPAD * 4);
#pragma unroll
        for (int i = 0; i < 4; i++) {
            int idx = t + i * 256;             // 0..1023
            int cr = idx >> 6, o4 = idx & 63;
            unsigned dst = wb + (cr * WPAD + o4 * 4) * 4;
            asm volatile("cp.async.cg.shared.global [%0], [%1], 16;"
                         :: "r"(dst), "l"(srcW + cr * OB + o4 * 4));
        }
        if (t < 128) {
            int cr = t >> 3, n4 = t & 7;
            unsigned dst = xb0 + buf * (16 * XPAD * 4) + (cr * XPAD + n4 * 4) * 4;
            asm volatile("cp.async.cg.shared.global [%0], [%1], 16;"
                :: "r"(dst), "l"(g_X + (size_t)(k * 16 + cr) * NP + bx * 32 + n4 * 4));
        }
        asm volatile("cp.async.commit_group;");
    };

    float acc[2][4][4];
#pragma unroll
    for (int a = 0; a < 2; a++)
#pragma unroll
        for (int b = 0; b < 4; b++)
#pragma unroll
            for (int r = 0; r < 4; r++) acc[a][b][r] = 0.f;

    load_chunk(0, 0);
    for (int k = 0; k < 64; k++) {
        int buf = k & 1;
        if (k < 63) {
            load_chunk(k + 1, buf ^ 1);
            asm volatile("cp.async.wait_group 1;");
        } else {
            asm volatile("cp.async.wait_group 0;");
        }
        __syncthreads();

#pragma unroll
        for (int s = 0; s < 2; s++) {
            int kl = s * 8;
            unsigned bf[4][2];
#pragma unroll
            for (int nt = 0; nt < 4; nt++) {
                bf[nt][0] = __float_as_uint(Xs[buf][kl + lr][nt * 8 + lq]);
                bf[nt][1] = __float_as_uint(Xs[buf][kl + lr + 4][nt * 8 + lq]);
            }
#pragma unroll
            for (int mi = 0; mi < 2; mi++) {
                int ob = (w * 2 + mi) * 16 + lq;
                unsigned a0 = __float_as_uint(Ws[buf][kl + lr][ob]);
                unsigned a1 = __float_as_uint(Ws[buf][kl + lr][ob + 8]);
                unsigned a2 = __float_as_uint(Ws[buf][kl + lr + 4][ob]);
                unsigned a3 = __float_as_uint(Ws[buf][kl + lr + 4][ob + 8]);
#pragma unroll
                for (int nt = 0; nt < 4; nt++) {
                    asm("mma.sync.aligned.m16n8k8.row.col.f32.tf32.tf32.f32 "
                        "{%0,%1,%2,%3}, {%4,%5,%6,%7}, {%8,%9}, {%0,%1,%2,%3};"
                        : "+f"(acc[mi][nt][0]), "+f"(acc[mi][nt][1]),
                          "+f"(acc[mi][nt][2]), "+f"(acc[mi][nt][3])
                        : "r"(a0), "r"(a1), "r"(a2), "r"(a3),
                          "r"(bf[nt][0]), "r"(bf[nt][1]));
                }
            }
        }
        __syncthreads();
    }

    // ---- epilogue: bias, per-np sum & max over all o (g_X already means) ----
    float br0 = __ldg(b1 + w * 32 + lq);
    float br1 = __ldg(b1 + w * 32 + lq + 8);
    float br2 = __ldg(b1 + w * 32 + 16 + lq);
    float br3 = __ldg(b1 + w * 32 + 16 + lq + 8);

#pragma unroll
    for (int nt = 0; nt < 4; nt++) {
        float he0 = acc[0][nt][0] + br0;
        float ho0 = acc[0][nt][1] + br0;
        float he1 = acc[0][nt][2] + br1;
        float ho1 = acc[0][nt][3] + br1;
        float he2 = acc[1][nt][0] + br2;
        float ho2 = acc[1][nt][1] + br2;
        float he3 = acc[1][nt][2] + br3;
        float ho3 = acc[1][nt][3] + br3;
        float se = he0 + he1 + he2 + he3;
        float so = ho0 + ho1 + ho2 + ho3;
        float me = fmaxf(fmaxf(he0, he1), fmaxf(he2, he3));
        float mo = fmaxf(fmaxf(ho0, ho1), fmaxf(ho2, ho3));
#pragma unroll
        for (int off = 4; off < 32; off <<= 1) {
            se += __shfl_xor_sync(0xffffffffu, se, off);
            so += __shfl_xor_sync(0xffffffffu, so, off);
            me = fmaxf(me, __shfl_xor_sync(0xffffffffu, me, off));
            mo = fmaxf(mo, __shfl_xor_sync(0xffffffffu, mo, off));
        }
        if (lq == 0) {
            red[w][nt * 8 + 2 * lr]     = make_float2(se, me);
            red[w][nt * 8 + 2 * lr + 1] = make_float2(so, mo);
        }
    }
    __syncthreads();
    if (t < 32) {
        float s = 0.f, m = -3.402823e38f;
#pragma unroll
        for (int ww = 0; ww < 8; ww++) {
            float2 v = red[ww][t];
            s += v.x;
            m = fmaxf(m, v.y);
        }
        pool_s[t] = make_float2(s, m);
    }
    __syncthreads();

    // ---- fused conv2 + softmax: this block's 32 np = 4 complete n ----
    if (t < 4) {
        int n = bx * 4 + t;
        float w2a = __ldg(w2), w2b = __ldg(w2 + 1), bb = __ldg(b2c);
        float lg[PB];
        float mxv = -3.402823e38f;
#pragma unroll
        for (int p = 0; p < PB; p++) {
            float2 v = pool_s[t * 8 + p];
            lg[p] = fmaf(w2a, v.x * (1.f / 256.f), fmaf(w2b, v.y, bb));
            mxv = fmaxf(mxv, lg[p]);
        }
        float e[PB], ssum = 0.f;
#pragma unroll
        for (int p = 0; p < PB; p++) { e[p] = expf(lg[p] - mxv); ssum += e[p]; }
        float inv = 1.f / ssum;
        float av[PB];
#pragma unroll
        for (int p = 0; p < PB; p++) {
            av[p] = e[p] * inv;
            g_att[n * 8 + p] = av[p];
        }
        g_att[n * 8 + 7] = 0.f;
        attj_store<0>(g_attj + (size_t)n * VB, av);
    }
}

// ---------------- kC: BN sums + fused last-block scale/shift ----------------
// grid (4, 32): x -> channel chunk (256 ch), y -> n chunk (16).
__global__ void __launch_bounds__(256) kC(const float* __restrict__ gamma,
                                          const float* __restrict__ beta) {
    __shared__ float sa[16][8];    // att * count[p]  (mean sums over g_X)
    __shared__ float sa2[16][8];   // att^2           (raw S2 sums)
    __shared__ int is_last;
    int c = blockIdx.x * 256 + threadIdx.x;
    int n0 = blockIdx.y * 16;

    if (threadIdx.x < 16) {
        int n = n0 + threadIdx.x;
        float4 a03 = __ldg((const float4*)(g_att + n * 8));
        float4 a47 = __ldg((const float4*)(g_att + n * 8) + 1);
        float av[8] = {a03.x, a03.y, a03.z, a03.w, a47.x, a47.y, a47.z, 0.f};
        const float cnt[7] = {17.f, 5.f, 5.f, 9.f, 6.f, 6.f, 20.f};
#pragma unroll
        for (int p = 0; p < PB; p++) {
            sa[threadIdx.x][p] = av[p] * cnt[p];
            sa2[threadIdx.x][p] = av[p] * av[p];
        }
        sa[threadIdx.x][7] = 0.f;
        sa2[threadIdx.x][7] = 0.f;
    }
    __syncthreads();

    float sY = 0.f, sY2 = 0.f;
    const float4* px = (const float4*)(g_X + (size_t)c * NP + n0 * 8);
#pragma unroll 4
    for (int nn = 0; nn < 16; nn++) {
        float4 q0 = __ldg(px + nn * 2), q1 = __ldg(px + nn * 2 + 1);
        uint4 u = __ldg((const uint4*)(g_S2h + ((size_t)(n0 + nn) * CB + c) * 4));
        float2 r0 = __half22float2(*(__half2*)&u.x);
        float2 r1 = __half22float2(*(__half2*)&u.y);
        float2 r2 = __half22float2(*(__half2*)&u.z);
        float2 r3 = __half22float2(*(__half2*)&u.w);
        const float* a  = sa[nn];
        const float* a2 = sa2[nn];
        sY  = fmaf(q0.x, a[0], fmaf(q0.y, a[1], fmaf(q0.z, a[2], fmaf(q0.w, a[3],
              fmaf(q1.x, a[4], fmaf(q1.y, a[5], fmaf(q1.z, a[6], sY)))))));
        sY2 = fmaf(r0.x, a2[0], fmaf(r0.y, a2[1], fmaf(r1.x, a2[2], fmaf(r1.y, a2[3],
              fmaf(r2.x, a2[4], fmaf(r2.y, a2[5], fmaf(r3.x, a2[6], sY2)))))));
    }
    size_t oidx = ((size_t)blockIdx.y * CB + c) * 2;
    g_part[oidx]     = sY;
    g_part[oidx + 1] = sY2;

    // ---- last-block reduction for this channel chunk ----
    __threadfence();
    if (threadIdx.x == 0)
        is_last = (atomicAdd(&g_cnt[blockIdx.x], 1) == 31);
    __syncthreads();
    if (is_last) {
        float tY = 0.f, tY2 = 0.f;
#pragma unroll
        for (int w = 0; w < 32; w++) {
            float2 v = __ldcg((const float2*)(g_part + ((size_t)w * CB + c) * 2));
            tY += v.x;
            tY2 += v.y;
        }
        const float inv = 1.f / (512.f * 68.f);
        float mean = tY * inv;
        float var = fmaf(-mean, mean, tY2 * inv);
        float sc = __ldg(gamma + c) * rsqrtf(var + 1e-5f);
        g_ss[c] = make_float2(sc, fmaf(-mean, sc, __ldg(beta + c)));
        if (threadIdx.x == 0) atomicExch(&g_cnt[blockIdx.x], 0);  // graph-safe
    }
}

// ---------------- kD: streaming scale+BN+residual+ReLU (no smem) ------------
// 4096 blocks x 128 threads, reverse order. Each block = 128 rows = one n.
__global__ void __launch_bounds__(128) kD(const float* __restrict__ x,
                                          float* __restrict__ out) {
    int t = threadIdx.x;
    int bid = 4095 - blockIdx.x;           // reverse: reuse x tail from L2
    int n = bid >> 3;                      // 8 blocks per n
    int c0 = (bid & 7) * 128;

    size_t base = (size_t)bid * 2176;      // float4 units (128*17)
    const float4* gx = (const float4*)x + base;
    float4* go = (float4*)out + base;
    const float4* aj = (const float4*)(g_attj + (size_t)n * VB);

#pragma unroll
    for (int i = 0; i < 17; i++) {
        int g = i * 128 + t;               // 0..2175
        int r = g / 17;                    // magic-mul
        int s = g - r * 17;
        float4 q = __ldg(gx + g);
        float4 a = __ldg(aj + s);
        float2 ss = __ldg(&g_ss[c0 + r]);
        q.x = fmaxf(fmaf(q.x, fmaf(a.x, ss.x, 1.f), ss.y), 0.f);
        q.y = fmaxf(fmaf(q.y, fmaf(a.y, ss.x, 1.f), ss.y), 0.f);
        q.z = fmaxf(fmaf(q.z, fmaf(a.z, ss.x, 1.f), ss.y), 0.f);
        q.w = fmaxf(fmaf(q.w, fmaf(a.w, ss.x, 1.f), ss.y), 0.f);
        __stcs(go + g, q);                 // streaming: keep L2 for x
    }
}

// ---------------- launch ----------------------------------------------------
extern "C" void kernel_launch(void* const* d_in, const int* in_sizes, int n_in,
                              void* d_out, int out_size) {
    const float* x     = (const float*)d_in[0];  // (512,1024,1,68)
    const float* w1    = (const float*)d_in[1];  // (256,1024)
    const float* b1    = (const float*)d_in[2];  // (256,)
    const float* w2    = (const float*)d_in[3];  // (2,)
    const float* b2    = (const float*)d_in[4];  // scalar
    const float* gamma = (const float*)d_in[5];  // (1024,)
    const float* beta  = (const float*)d_in[6];  // (1024,)
    float* out = (float*)d_out;

    kAT<<<4096 + 2048, 128>>>(x, w1);
    kB<<<128, 256>>>(b1, w2, b2);
    kC<<<dim3(4, 32), 256>>>(gamma, beta);
    kD<<<4096, 128>>>(x, out);
}